// round 3
// baseline (speedup 1.0000x reference)
#include <cuda_runtime.h>

#define NN 50000
#define EE 800000
#define ET (EE + NN)          // edges + self loops
#define FIN 64
#define HID 64
#define HEADS 4
#define C1 256                // HEADS*HID
#define GG 64
#define NCLS 3
#define EPSBN 1e-5f
#define SLOPE 0.2f

// ---------------- scratch (device globals; no allocations allowed) ----------
__device__ __align__(16) float g_h1[NN * C1];     // layer1 pre-agg features
__device__ __align__(16) float g_out1[NN * C1];   // layer1 unnormalized aggregate
__device__ __align__(16) float g_es1[NN * HEADS];
__device__ __align__(16) float g_ed1[NN * HEADS];
__device__ __align__(16) float g_den1[NN * HEADS];
__device__ __align__(16) float g_h2[NN * HID];
__device__ __align__(16) float g_out2[NN * HID];
__device__ float g_es2[NN];
__device__ float g_ed2[NN];
__device__ float g_den2[NN];
__device__ float g_pool[GG * HID];
__device__ float g_cnt[GG];
__device__ int   g_is64;

// vectorized no-return global reduction (sm_90+)
__device__ __forceinline__ void red_add_v4(float* addr, float a, float b, float c, float d) {
    asm volatile("red.global.add.v4.f32 [%0], {%1,%2,%3,%4};"
                 :: "l"(addr), "f"(a), "f"(b), "f"(c), "f"(d) : "memory");
}
__device__ __forceinline__ void red_add_f32(float* addr, float a) {
    asm volatile("red.global.add.f32 [%0], %1;" :: "l"(addr), "f"(a) : "memory");
}

__device__ __forceinline__ float lrelu(float t) { return t > 0.f ? t : SLOPE * t; }

// ---------------- index dtype detection (int32 vs int64 storage) ------------
__global__ void k_detect(const int* ei) {
    if (blockIdx.x == 0 && threadIdx.x == 0) {
        // int64 storage: hi-words (odd 32-bit positions) are all 0 (values < 2^31).
        // int32 storage: odd positions are random node ids -> essentially never all 0.
        int all0 = 1;
        for (int i = 0; i < 64; i++) {
            if (ei[2 * i + 1] != 0) { all0 = 0; break; }
        }
        g_is64 = all0;
    }
}

__device__ __forceinline__ int ld_idx(const int* p, int i) {
    return p[g_is64 ? 2 * i : i];
}

// ---------------- zero accumulators ----------------------------------------
__global__ void k_zero() {
    int i = blockIdx.x * blockDim.x + threadIdx.x;
    int stride = gridDim.x * blockDim.x;
    for (int j = i; j < NN * C1; j += stride)    g_out1[j] = 0.f;
    for (int j = i; j < NN * HEADS; j += stride) g_den1[j] = 0.f;
    for (int j = i; j < NN * HID; j += stride)   g_out2[j] = 0.f;
    for (int j = i; j < NN; j += stride)         g_den2[j] = 0.f;
    for (int j = i; j < GG * HID; j += stride)   g_pool[j] = 0.f;
    for (int j = i; j < GG; j += stride)         g_cnt[j] = 0.f;
}

// ---------------- layer 1: x @ W1, per-node attention scores ----------------
// block = node, 256 threads (one per output channel)
__global__ void k_gemm1(const float* __restrict__ x, const float* __restrict__ W1,
                        const float* __restrict__ a_s, const float* __restrict__ a_d) {
    __shared__ float sx[FIN];
    __shared__ float s_es[HEADS], s_ed[HEADS];
    int n = blockIdx.x;
    int t = threadIdx.x;
    if (t < FIN) sx[t] = x[n * FIN + t];
    if (t < HEADS) { s_es[t] = 0.f; s_ed[t] = 0.f; }
    __syncthreads();
    float acc = 0.f;
#pragma unroll
    for (int k = 0; k < FIN; k++)
        acc = fmaf(sx[k], __ldg(&W1[k * C1 + t]), acc);
    g_h1[n * C1 + t] = acc;
    int h = t >> 6, c = t & 63;
    float vs = acc * __ldg(&a_s[h * HID + c]);
    float vd = acc * __ldg(&a_d[h * HID + c]);
#pragma unroll
    for (int o = 16; o > 0; o >>= 1) {
        vs += __shfl_down_sync(0xffffffffu, vs, o);
        vd += __shfl_down_sync(0xffffffffu, vd, o);
    }
    if ((t & 31) == 0) { atomicAdd(&s_es[h], vs); atomicAdd(&s_ed[h], vd); }
    __syncthreads();
    if (t < HEADS) {
        g_es1[n * HEADS + t] = s_es[t];
        g_ed1[n * HEADS + t] = s_ed[t];
    }
}

// ---------------- layer 1: weighted scatter + denom (warp per edge) ---------
__global__ void k_scat1(const int* __restrict__ ei) {
    int gid = blockIdx.x * blockDim.x + threadIdx.x;
    int e = gid >> 5, lane = gid & 31;
    if (e >= ET) return;
    int s, d;
    if (e < EE) { s = ld_idx(ei, e); d = ld_idx(ei, EE + e); }
    else        { s = e - EE; d = s; }
    int h = lane >> 3;                         // 8 lanes per head
    float p = expf(lrelu(g_es1[s * 4 + h] + g_ed1[d * 4 + h]));
    if ((lane & 7) == 0) red_add_f32(g_den1 + d * 4 + h, p);   // fused denominator
    const float4* hs = (const float4*)(g_h1 + s * C1 + lane * 8);
    float4 a = hs[0], b = hs[1];
    red_add_v4(g_out1 + d * C1 + lane * 8,     a.x * p, a.y * p, a.z * p, a.w * p);
    red_add_v4(g_out1 + d * C1 + lane * 8 + 4, b.x * p, b.y * p, b.z * p, b.w * p);
}

// ---------------- normalize + bias + BN1 + ELU, then h @ W2 + scores --------
__global__ void k_mid(const float* __restrict__ b1, const float* __restrict__ g1,
                      const float* __restrict__ be1, const float* __restrict__ m1,
                      const float* __restrict__ v1, const float* __restrict__ W2,
                      const float* __restrict__ as2, const float* __restrict__ ad2) {
    __shared__ float y[C1];
    __shared__ float sred[2];
    int n = blockIdx.x, t = threadIdx.x;
    float den = g_den1[n * HEADS + (t >> 6)];
    float val = g_out1[n * C1 + t] / den + __ldg(&b1[t]);
    val = (val - __ldg(&m1[t])) * rsqrtf(__ldg(&v1[t]) + EPSBN) * __ldg(&g1[t]) + __ldg(&be1[t]);
    val = val > 0.f ? val : expm1f(val);       // ELU
    y[t] = val;
    if (t < 2) sred[t] = 0.f;
    __syncthreads();
    float acc = 0.f, vs = 0.f, vd = 0.f;
    if (t < HID) {
#pragma unroll 8
        for (int k = 0; k < C1; k++)
            acc = fmaf(y[k], __ldg(&W2[k * HID + t]), acc);
        g_h2[n * HID + t] = acc;
        vs = acc * __ldg(&as2[t]);
        vd = acc * __ldg(&ad2[t]);
    }
#pragma unroll
    for (int o = 16; o > 0; o >>= 1) {
        vs += __shfl_down_sync(0xffffffffu, vs, o);
        vd += __shfl_down_sync(0xffffffffu, vd, o);
    }
    if ((t & 31) == 0 && t < HID) { atomicAdd(&sred[0], vs); atomicAdd(&sred[1], vd); }
    __syncthreads();
    if (t == 0) { g_es2[n] = sred[0]; g_ed2[n] = sred[1]; }
}

// ---------------- layer 2: weighted scatter + denom (16 lanes per edge) -----
__global__ void k_scat2(const int* __restrict__ ei) {
    int gid = blockIdx.x * blockDim.x + threadIdx.x;
    int e = gid >> 4, l = gid & 15;
    if (e >= ET) return;
    int s, d;
    if (e < EE) { s = ld_idx(ei, e); d = ld_idx(ei, EE + e); }
    else        { s = e - EE; d = s; }
    float p = expf(lrelu(g_es2[s] + g_ed2[d]));
    if (l == 0) red_add_f32(g_den2 + d, p);                    // fused denominator
    float4 v = *(const float4*)(g_h2 + s * HID + l * 4);
    red_add_v4(g_out2 + d * HID + l * 4, v.x * p, v.y * p, v.z * p, v.w * p);
}

// ---------------- normalize + bias + BN2 + mean-pool scatter ----------------
__global__ void k_pool(const int* __restrict__ batch, const float* __restrict__ b2,
                       const float* __restrict__ g2, const float* __restrict__ be2,
                       const float* __restrict__ m2, const float* __restrict__ v2) {
    int idx = blockIdx.x * blockDim.x + threadIdx.x;
    if (idx >= NN * HID) return;
    int n = idx >> 6, ch = idx & 63;
    int g = ld_idx(batch, n);
    float val = g_out2[idx] / g_den2[n] + __ldg(&b2[ch]);
    val = (val - __ldg(&m2[ch])) * rsqrtf(__ldg(&v2[ch]) + EPSBN) * __ldg(&g2[ch]) + __ldg(&be2[ch]);
    atomicAdd(&g_pool[g * HID + ch], val);
    if (ch == 0) atomicAdd(&g_cnt[g], 1.f);
}

// ---------------- MLP head + log_softmax ------------------------------------
__global__ void k_head(const float* __restrict__ lw1, const float* __restrict__ lb1,
                       const float* __restrict__ lw2, const float* __restrict__ lb2,
                       float* __restrict__ out) {
    int g = threadIdx.x;
    if (g >= GG) return;
    float inv = 1.f / fmaxf(g_cnt[g], 1.f);
    float z1[HID / 2];
#pragma unroll 4
    for (int j = 0; j < HID / 2; j++) {
        float a = lb1[j];
        for (int k = 0; k < HID; k++)
            a = fmaf(g_pool[g * HID + k] * inv, lw1[k * (HID / 2) + j], a);
        z1[j] = fmaxf(a, 0.f);
    }
    float z2[NCLS];
#pragma unroll
    for (int c = 0; c < NCLS; c++) {
        float a = lb2[c];
        for (int j = 0; j < HID / 2; j++)
            a = fmaf(z1[j], lw2[j * NCLS + c], a);
        z2[c] = a;
    }
    float mx = fmaxf(z2[0], fmaxf(z2[1], z2[2]));
    float lse = mx + logf(expf(z2[0] - mx) + expf(z2[1] - mx) + expf(z2[2] - mx));
#pragma unroll
    for (int c = 0; c < NCLS; c++) out[g * NCLS + c] = z2[c] - lse;
}

// ---------------- host launcher ---------------------------------------------
extern "C" void kernel_launch(void* const* d_in, const int* in_sizes, int n_in,
                              void* d_out, int out_size) {
    // Resolve input ordering at runtime:
    //  dict order (setup_inputs): [x, edge_index, batch, W1, as1, ad1, b1, g1, be1, m1, v1,
    //                              W2, as2, ad2, b2, g2, be2, m2, v2, lw1, lb1, lw2, lb2]
    //  signature order:           [x, W1, as1, ad1, b1, g1, be1, m1, v1, W2, as2, ad2, b2,
    //                              g2, be2, m2, v2, lw1, lb1, lw2, lb2, edge_index, batch]
    int IX, IEI, IB, IW1, IAS1, IAD1, IB1, IG1, IBE1, IM1, IV1,
        IW2, IAS2, IAD2, IB2, IG2, IBE2, IM2, IV2, ILW1, ILB1, ILW2, ILB2;
    if (n_in >= 3 && in_sizes[1] == 2 * EE) {
        IX = 0; IEI = 1; IB = 2; IW1 = 3; IAS1 = 4; IAD1 = 5; IB1 = 6; IG1 = 7; IBE1 = 8;
        IM1 = 9; IV1 = 10; IW2 = 11; IAS2 = 12; IAD2 = 13; IB2 = 14; IG2 = 15; IBE2 = 16;
        IM2 = 17; IV2 = 18; ILW1 = 19; ILB1 = 20; ILW2 = 21; ILB2 = 22;
    } else {
        IX = 0; IW1 = 1; IAS1 = 2; IAD1 = 3; IB1 = 4; IG1 = 5; IBE1 = 6; IM1 = 7; IV1 = 8;
        IW2 = 9; IAS2 = 10; IAD2 = 11; IB2 = 12; IG2 = 13; IBE2 = 14; IM2 = 15; IV2 = 16;
        ILW1 = 17; ILB1 = 18; ILW2 = 19; ILB2 = 20; IEI = 21; IB = 22;
    }

    const float* x   = (const float*)d_in[IX];
    const int*   ei  = (const int*)d_in[IEI];    // 32-bit view; dtype detected on device
    const int*   bat = (const int*)d_in[IB];
    const float* W1  = (const float*)d_in[IW1];
    const float* as1 = (const float*)d_in[IAS1];
    const float* ad1 = (const float*)d_in[IAD1];
    const float* b1  = (const float*)d_in[IB1];
    const float* g1  = (const float*)d_in[IG1];
    const float* be1 = (const float*)d_in[IBE1];
    const float* m1  = (const float*)d_in[IM1];
    const float* v1  = (const float*)d_in[IV1];
    const float* W2  = (const float*)d_in[IW2];
    const float* as2 = (const float*)d_in[IAS2];
    const float* ad2 = (const float*)d_in[IAD2];
    const float* b2  = (const float*)d_in[IB2];
    const float* g2  = (const float*)d_in[IG2];
    const float* be2 = (const float*)d_in[IBE2];
    const float* m2  = (const float*)d_in[IM2];
    const float* v2  = (const float*)d_in[IV2];
    const float* lw1 = (const float*)d_in[ILW1];
    const float* lb1 = (const float*)d_in[ILB1];
    const float* lw2 = (const float*)d_in[ILW2];
    const float* lb2 = (const float*)d_in[ILB2];
    float* out = (float*)d_out;

    k_detect<<<1, 32>>>(ei);
    k_zero<<<2048, 256>>>();
    k_gemm1<<<NN, 256>>>(x, W1, as1, ad1);
    k_scat1<<<(ET * 32 + 255) / 256, 256>>>(ei);
    k_mid<<<NN, 256>>>(b1, g1, be1, m1, v1, W2, as2, ad2);
    k_scat2<<<(ET * 16 + 255) / 256, 256>>>(ei);
    k_pool<<<(NN * HID + 255) / 256, 256>>>(bat, b2, g2, be2, m2, v2);
    k_head<<<1, 64>>>(lw1, lb1, lw2, lb2, out);
}

// round 5
// speedup vs baseline: 1.4127x; 1.4127x over previous
#include <cuda_runtime.h>

#define NN 50000
#define EE 800000
#define FIN 64
#define HID 64
#define HEADS 4
#define C1 256
#define GG 64
#define NCLS 3
#define EPSBN 1e-5f
#define SLOPE 0.2f

#define NB_GEMM 3125          // 50000/16 nodes-per-block
#define SCAN_BLOCKS 196       // ceil(50000/256)

// ---------------- scratch ----------------------------------------------------
__device__ __align__(16) float g_h1[NN * C1];
__device__ __align__(16) float g_y[NN * C1];
__device__ __align__(16) float g_es1[NN * HEADS];
__device__ __align__(16) float g_ed1[NN * HEADS];
__device__ __align__(16) float g_h2[NN * HID];
__device__ float g_es2[NN];
__device__ float g_ed2[NN];
__device__ float g_pool[GG * HID];
__device__ float g_cnt[GG];
__device__ int   g_deg[NN];
__device__ int   g_off[NN + 1];
__device__ int   g_cur[NN];
__device__ int   g_srcs[EE];
__device__ int   g_bsum[SCAN_BLOCKS];
__device__ int   g_boff[SCAN_BLOCKS];
__device__ int   g_is64;

__device__ __forceinline__ void red_add_f32(float* addr, float a) {
    asm volatile("red.global.add.f32 [%0], %1;" :: "l"(addr), "f"(a) : "memory");
}
__device__ __forceinline__ float lrelu(float t) { return t > 0.f ? t : SLOPE * t; }

// ---------------- index dtype detection --------------------------------------
__global__ void k_detect(const int* ei) {
    if (threadIdx.x == 0) {
        int all0 = 1;
        for (int i = 0; i < 64; i++)
            if (ei[2 * i + 1] != 0) { all0 = 0; break; }
        g_is64 = all0;
    }
}
__device__ __forceinline__ int ld_idx(const int* p, int i) {
    return p[g_is64 ? 2 * i : i];
}

// ---------------- zero small accumulators ------------------------------------
__global__ void k_zero() {
    int i = blockIdx.x * blockDim.x + threadIdx.x;
    int stride = gridDim.x * blockDim.x;
    for (int j = i; j < NN; j += stride)       g_deg[j] = 0;
    for (int j = i; j < GG * HID; j += stride) g_pool[j] = 0.f;
    for (int j = i; j < GG; j += stride)       g_cnt[j] = 0.f;
}

// ---------------- CSR build ---------------------------------------------------
__global__ void k_deg(const int* __restrict__ ei) {
    int e = blockIdx.x * blockDim.x + threadIdx.x;
    if (e >= EE) return;
    atomicAdd(&g_deg[ld_idx(ei, EE + e)], 1);
}
__global__ void k_scanA() {
    __shared__ int s[256];
    int t = threadIdx.x;
    int i = blockIdx.x * 256 + t;
    int v = (i < NN) ? g_deg[i] : 0;
    s[t] = v; __syncthreads();
    for (int o = 1; o < 256; o <<= 1) {
        int u = (t >= o) ? s[t - o] : 0;
        __syncthreads(); s[t] += u; __syncthreads();
    }
    if (i < NN) g_off[i] = s[t] - v;
    if (t == 255) g_bsum[blockIdx.x] = s[255];
}
__global__ void k_scanB() {
    __shared__ int s[256];
    int t = threadIdx.x;
    int v = (t < SCAN_BLOCKS) ? g_bsum[t] : 0;
    s[t] = v; __syncthreads();
    for (int o = 1; o < 256; o <<= 1) {
        int u = (t >= o) ? s[t - o] : 0;
        __syncthreads(); s[t] += u; __syncthreads();
    }
    if (t < SCAN_BLOCKS) g_boff[t] = s[t] - v;
    if (t == 0) g_off[NN] = EE;
}
__global__ void k_scanC() {
    int i = blockIdx.x * 256 + threadIdx.x;
    if (i >= NN) return;
    int o = g_off[i] + g_boff[blockIdx.x];
    g_off[i] = o;
    g_cur[i] = o;
}
__global__ void k_fill(const int* __restrict__ ei) {
    int e = blockIdx.x * blockDim.x + threadIdx.x;
    if (e >= EE) return;
    int s = ld_idx(ei, e);
    int d = ld_idx(ei, EE + e);
    int pos = atomicAdd(&g_cur[d], 1);
    g_srcs[pos] = s;
}

// ---------------- GEMM1: x @ W1 (+ per-node attention scores) ----------------
// 16 nodes/block, 256 threads (thread = output channel). W1 staged in smem in
// two k-halves, transposed (pad 36) for conflict-free float4 reads.
__global__ void k_gemm1(const float* __restrict__ x, const float* __restrict__ W1,
                        const float* __restrict__ a_s, const float* __restrict__ a_d) {
    __shared__ float sx[16 * 64];        // 4 KB
    __shared__ float sW1T[256 * 36];     // 36 KB (one 32-k half, [c][k] padded)
    __shared__ float ses[16 * 4], sed[16 * 4];
    int n0 = blockIdx.x * 16;
    int t = threadIdx.x;
    for (int i = t; i < 16 * 64 / 4; i += 256)
        ((float4*)sx)[i] = ((const float4*)(x + n0 * 64))[i];
    if (t < 64) { ses[t] = 0.f; sed[t] = 0.f; }
    float acc[16];
#pragma unroll
    for (int n = 0; n < 16; n++) acc[n] = 0.f;
    for (int half = 0; half < 2; half++) {
        __syncthreads();
        for (int i = t; i < 32 * 256; i += 256) {
            int kk = i >> 8, cc = i & 255;
            sW1T[cc * 36 + kk] = W1[(half * 32 + kk) * 256 + cc];
        }
        __syncthreads();
#pragma unroll
        for (int k4 = 0; k4 < 8; k4++) {
            float4 w = *(float4*)&sW1T[t * 36 + k4 * 4];
#pragma unroll
            for (int n = 0; n < 16; n++) {
                float4 xv = *(float4*)&sx[n * 64 + half * 32 + k4 * 4];
                acc[n] = fmaf(w.x, xv.x, acc[n]);
                acc[n] = fmaf(w.y, xv.y, acc[n]);
                acc[n] = fmaf(w.z, xv.z, acc[n]);
                acc[n] = fmaf(w.w, xv.w, acc[n]);
            }
        }
    }
    __syncthreads();
    int h = t >> 6, c = t & 63;
    float asv = __ldg(&a_s[h * 64 + c]);
    float adv = __ldg(&a_d[h * 64 + c]);
#pragma unroll
    for (int n = 0; n < 16; n++) {
        g_h1[(n0 + n) * C1 + t] = acc[n];
        float vs = acc[n] * asv, vd = acc[n] * adv;
#pragma unroll
        for (int o = 16; o > 0; o >>= 1) {
            vs += __shfl_down_sync(0xffffffffu, vs, o);
            vd += __shfl_down_sync(0xffffffffu, vd, o);
        }
        if ((t & 31) == 0) { atomicAdd(&ses[n * 4 + h], vs); atomicAdd(&sed[n * 4 + h], vd); }
    }
    __syncthreads();
    if (t < 64) {
        int n = t >> 2, hh = t & 3;
        g_es1[(n0 + n) * 4 + hh] = ses[t];
        g_ed1[(n0 + n) * 4 + hh] = sed[t];
    }
}

// ---------------- Layer-1 aggregate per dst (CSR) + BN1 + ELU ----------------
// block = dst node, 256 threads = channels. Tiled: 32 edges/tile, probabilities
// precomputed by 128 threads, then register accumulation + denominator.
__global__ void k_agg1(const float* __restrict__ b1, const float* __restrict__ g1,
                       const float* __restrict__ be1, const float* __restrict__ m1,
                       const float* __restrict__ v1) {
    __shared__ int   ssrc[32];
    __shared__ float sp[32 * 4];
    int d = blockIdx.x;
    int t = threadIdx.x;
    int off = g_off[d];
    int deg = g_off[d + 1] - off;
    int hsel = t >> 6;
    float acc = 0.f, den = 0.f;
    for (int base = 0; base < deg; base += 32) {
        int m = min(32, deg - base);
        if (t < m * 4) {
            int e = t >> 2, hh = t & 3;
            int s = g_srcs[off + base + e];
            if (hh == 0) ssrc[e] = s;
            sp[t] = __expf(lrelu(g_es1[s * 4 + hh] + g_ed1[d * 4 + hh]));
        }
        __syncthreads();
#pragma unroll 2
        for (int e = 0; e < m; e++) {
            float p = sp[e * 4 + hsel];
            int s = ssrc[e];
            acc = fmaf(p, g_h1[s * C1 + t], acc);
            den += p;
        }
        __syncthreads();
    }
    float ps = __expf(lrelu(g_es1[d * 4 + hsel] + g_ed1[d * 4 + hsel]));
    acc = fmaf(ps, g_h1[d * C1 + t], acc);
    den += ps;
    float val = acc / den + __ldg(&b1[t]);
    val = (val - __ldg(&m1[t])) * rsqrtf(__ldg(&v1[t]) + EPSBN) * __ldg(&g1[t]) + __ldg(&be1[t]);
    val = val > 0.f ? val : expm1f(val);
    g_y[d * C1 + t] = val;
}

// ---------------- GEMM2: y @ W2 (+ layer-2 scores) ---------------------------
// 16 nodes/block. W2 staged in 4 k-quarters, transposed (pad 68) for float4.
__global__ void k_mid(const float* __restrict__ W2, const float* __restrict__ as2,
                      const float* __restrict__ ad2) {
    __shared__ float sy[16 * 256];       // 16 KB
    __shared__ float sW2T[64 * 68];      // 17 KB ([c][k] quarter, padded)
    __shared__ float sh2[16 * 64];       // 4 KB
    int n0 = blockIdx.x * 16;
    int t = threadIdx.x;
    for (int i = t; i < 16 * 256 / 4; i += 256)
        ((float4*)sy)[i] = ((const float4*)(g_y + n0 * 256))[i];
    int c = t & 63, nq = t >> 6;
    float acc[4] = {0.f, 0.f, 0.f, 0.f};
    for (int q = 0; q < 4; q++) {
        __syncthreads();
        for (int i = t; i < 64 * 64; i += 256) {
            int kk = i >> 6, cc = i & 63;
            sW2T[cc * 68 + kk] = W2[(q * 64 + kk) * 64 + cc];
        }
        __syncthreads();
#pragma unroll
        for (int j = 0; j < 4; j++) {
            int n = nq + j * 4;
            float a = acc[j];
#pragma unroll
            for (int k4 = 0; k4 < 16; k4++) {
                float4 w  = *(float4*)&sW2T[c * 68 + k4 * 4];
                float4 yv = *(float4*)&sy[n * 256 + q * 64 + k4 * 4];
                a = fmaf(w.x, yv.x, a);
                a = fmaf(w.y, yv.y, a);
                a = fmaf(w.z, yv.z, a);
                a = fmaf(w.w, yv.w, a);
            }
            acc[j] = a;
        }
    }
    __syncthreads();
#pragma unroll
    for (int j = 0; j < 4; j++) {
        int n = nq + j * 4;
        g_h2[(n0 + n) * 64 + c] = acc[j];
        sh2[n * 64 + c] = acc[j];
    }
    __syncthreads();
    if (t < 16) {
        float vs = 0.f, vd = 0.f;
        for (int k = 0; k < 64; k++) {
            float hv = sh2[t * 64 + k];
            vs = fmaf(hv, __ldg(&as2[k]), vs);
            vd = fmaf(hv, __ldg(&ad2[k]), vd);
        }
        g_es2[n0 + t] = vs;
        g_ed2[n0 + t] = vd;
    }
}

// ---------------- Layer-2 aggregate per dst + BN2 + mean-pool scatter --------
// 4 dst nodes per block, 64 threads each; p computed redundantly per thread.
__global__ void k_agg2(const int* __restrict__ bat, const float* __restrict__ b2,
                       const float* __restrict__ g2, const float* __restrict__ be2,
                       const float* __restrict__ m2, const float* __restrict__ v2) {
    int t = threadIdx.x;
    int d = blockIdx.x * 4 + (t >> 6);
    int c = t & 63;
    int off = g_off[d];
    int deg = g_off[d + 1] - off;
    float edv = g_ed2[d];
    float acc = 0.f, den = 0.f;
    for (int j = 0; j < deg; j++) {
        int s = g_srcs[off + j];
        float p = __expf(lrelu(g_es2[s] + edv));
        acc = fmaf(p, g_h2[s * 64 + c], acc);
        den += p;
    }
    float ps = __expf(lrelu(g_es2[d] + edv));
    acc = fmaf(ps, g_h2[d * 64 + c], acc);
    den += ps;
    float val = acc / den + __ldg(&b2[c]);
    val = (val - __ldg(&m2[c])) * rsqrtf(__ldg(&v2[c]) + EPSBN) * __ldg(&g2[c]) + __ldg(&be2[c]);
    int g = ld_idx(bat, d);
    red_add_f32(&g_pool[g * 64 + c], val);
    if (c == 0) red_add_f32(&g_cnt[g], 1.f);
}

// ---------------- MLP head + log_softmax -------------------------------------
__global__ void k_head(const float* __restrict__ lw1, const float* __restrict__ lb1,
                       const float* __restrict__ lw2, const float* __restrict__ lb2,
                       float* __restrict__ out) {
    int g = threadIdx.x;
    if (g >= GG) return;
    float inv = 1.f / fmaxf(g_cnt[g], 1.f);
    float z1[HID / 2];
#pragma unroll 4
    for (int j = 0; j < HID / 2; j++) {
        float a = lb1[j];
        for (int k = 0; k < HID; k++)
            a = fmaf(g_pool[g * HID + k] * inv, lw1[k * (HID / 2) + j], a);
        z1[j] = fmaxf(a, 0.f);
    }
    float z2[NCLS];
#pragma unroll
    for (int cc = 0; cc < NCLS; cc++) {
        float a = lb2[cc];
        for (int j = 0; j < HID / 2; j++)
            a = fmaf(z1[j], lw2[j * NCLS + cc], a);
        z2[cc] = a;
    }
    float mx = fmaxf(z2[0], fmaxf(z2[1], z2[2]));
    float lse = mx + logf(expf(z2[0] - mx) + expf(z2[1] - mx) + expf(z2[2] - mx));
#pragma unroll
    for (int cc = 0; cc < NCLS; cc++) out[g * NCLS + cc] = z2[cc] - lse;
}

// ---------------- host launcher ----------------------------------------------
extern "C" void kernel_launch(void* const* d_in, const int* in_sizes, int n_in,
                              void* d_out, int out_size) {
    int IX, IEI, IB, IW1, IAS1, IAD1, IB1, IG1, IBE1, IM1, IV1,
        IW2, IAS2, IAD2, IB2, IG2, IBE2, IM2, IV2, ILW1, ILB1, ILW2, ILB2;
    if (n_in >= 3 && in_sizes[1] == 2 * EE) {
        IX = 0; IEI = 1; IB = 2; IW1 = 3; IAS1 = 4; IAD1 = 5; IB1 = 6; IG1 = 7; IBE1 = 8;
        IM1 = 9; IV1 = 10; IW2 = 11; IAS2 = 12; IAD2 = 13; IB2 = 14; IG2 = 15; IBE2 = 16;
        IM2 = 17; IV2 = 18; ILW1 = 19; ILB1 = 20; ILW2 = 21; ILB2 = 22;
    } else {
        IX = 0; IW1 = 1; IAS1 = 2; IAD1 = 3; IB1 = 4; IG1 = 5; IBE1 = 6; IM1 = 7; IV1 = 8;
        IW2 = 9; IAS2 = 10; IAD2 = 11; IB2 = 12; IG2 = 13; IBE2 = 14; IM2 = 15; IV2 = 16;
        ILW1 = 17; ILB1 = 18; ILW2 = 19; ILB2 = 20; IEI = 21; IB = 22;
    }

    const float* x   = (const float*)d_in[IX];
    const int*   ei  = (const int*)d_in[IEI];
    const int*   bat = (const int*)d_in[IB];
    const float* W1  = (const float*)d_in[IW1];
    const float* as1 = (const float*)d_in[IAS1];
    const float* ad1 = (const float*)d_in[IAD1];
    const float* b1  = (const float*)d_in[IB1];
    const float* g1  = (const float*)d_in[IG1];
    const float* be1 = (const float*)d_in[IBE1];
    const float* m1  = (const float*)d_in[IM1];
    const float* v1  = (const float*)d_in[IV1];
    const float* W2  = (const float*)d_in[IW2];
    const float* as2 = (const float*)d_in[IAS2];
    const float* ad2 = (const float*)d_in[IAD2];
    const float* b2  = (const float*)d_in[IB2];
    const float* g2  = (const float*)d_in[IG2];
    const float* be2 = (const float*)d_in[IBE2];
    const float* m2  = (const float*)d_in[IM2];
    const float* v2  = (const float*)d_in[IV2];
    const float* lw1 = (const float*)d_in[ILW1];
    const float* lb1 = (const float*)d_in[ILB1];
    const float* lw2 = (const float*)d_in[ILW2];
    const float* lb2 = (const float*)d_in[ILB2];
    float* out = (float*)d_out;

    k_detect<<<1, 32>>>(ei);
    k_zero<<<256, 256>>>();
    k_deg<<<(EE + 511) / 512, 512>>>(ei);
    k_scanA<<<SCAN_BLOCKS, 256>>>();
    k_scanB<<<1, 256>>>();
    k_scanC<<<SCAN_BLOCKS, 256>>>();
    k_fill<<<(EE + 511) / 512, 512>>>(ei);
    k_gemm1<<<NB_GEMM, 256>>>(x, W1, as1, ad1);
    k_agg1<<<NN, 256>>>(b1, g1, be1, m1, v1);
    k_mid<<<NB_GEMM, 256>>>(W2, as2, ad2);
    k_agg2<<<NN / 4, 256>>>(bat, b2, g2, be2, m2, v2);
    k_head<<<1, 64>>>(lw1, lb1, lw2, lb2, out);
}

// round 7
// speedup vs baseline: 1.4162x; 1.0025x over previous
#include <cuda_runtime.h>

#define NN 50000
#define EE 800000
#define FIN 64
#define HID 64
#define HEADS 4
#define C1 256
#define GG 64
#define NCLS 3
#define EPSBN 1e-5f
#define SLOPE 0.2f

#define NB_GEMM 3125          // 50000/16 nodes-per-block
#define SCAN_BLOCKS 196       // ceil(50000/256)

// ---------------- scratch ----------------------------------------------------
__device__ __align__(16) float g_h1[NN * C1];
__device__ __align__(16) float g_y[NN * C1];
__device__ __align__(16) float g_es1[NN * HEADS];
__device__ __align__(16) float g_ed1[NN * HEADS];
__device__ __align__(16) float g_h2[NN * HID];
__device__ float g_es2[NN];
__device__ float g_ed2[NN];
__device__ float g_pool[GG * HID];
__device__ float g_cnt[GG];
__device__ int   g_deg[NN];
__device__ int   g_off[NN + 1];
__device__ int   g_cur[NN];
__device__ int   g_srcs[EE];
__device__ int   g_bsum[SCAN_BLOCKS];
__device__ int   g_boff[SCAN_BLOCKS];
__device__ int   g_is64;

__device__ __forceinline__ void red_add_f32(float* addr, float a) {
    asm volatile("red.global.add.f32 [%0], %1;" :: "l"(addr), "f"(a) : "memory");
}
__device__ __forceinline__ float lrelu(float t) { return t > 0.f ? t : SLOPE * t; }

// ---------------- index dtype detection --------------------------------------
__global__ void k_detect(const int* ei) {
    if (threadIdx.x == 0) {
        int all0 = 1;
        for (int i = 0; i < 64; i++)
            if (ei[2 * i + 1] != 0) { all0 = 0; break; }
        g_is64 = all0;
    }
}
__device__ __forceinline__ int ld_idx(const int* p, int i) {
    return p[g_is64 ? 2 * i : i];
}

// ---------------- zero small accumulators ------------------------------------
__global__ void k_zero() {
    int i = blockIdx.x * blockDim.x + threadIdx.x;
    int stride = gridDim.x * blockDim.x;
    for (int j = i; j < NN; j += stride)       g_deg[j] = 0;
    for (int j = i; j < GG * HID; j += stride) g_pool[j] = 0.f;
    for (int j = i; j < GG; j += stride)       g_cnt[j] = 0.f;
}

// ---------------- CSR build ---------------------------------------------------
__global__ void k_deg(const int* __restrict__ ei) {
    int e = blockIdx.x * blockDim.x + threadIdx.x;
    if (e >= EE) return;
    atomicAdd(&g_deg[ld_idx(ei, EE + e)], 1);
}
__global__ void k_scanA() {
    __shared__ int s[256];
    int t = threadIdx.x;
    int i = blockIdx.x * 256 + t;
    int v = (i < NN) ? g_deg[i] : 0;
    s[t] = v; __syncthreads();
    for (int o = 1; o < 256; o <<= 1) {
        int u = (t >= o) ? s[t - o] : 0;
        __syncthreads(); s[t] += u; __syncthreads();
    }
    if (i < NN) g_off[i] = s[t] - v;
    if (t == 255) g_bsum[blockIdx.x] = s[255];
}
__global__ void k_scanB() {
    __shared__ int s[256];
    int t = threadIdx.x;
    int v = (t < SCAN_BLOCKS) ? g_bsum[t] : 0;
    s[t] = v; __syncthreads();
    for (int o = 1; o < 256; o <<= 1) {
        int u = (t >= o) ? s[t - o] : 0;
        __syncthreads(); s[t] += u; __syncthreads();
    }
    if (t < SCAN_BLOCKS) g_boff[t] = s[t] - v;
    if (t == 0) g_off[NN] = EE;
}
__global__ void k_scanC() {
    int i = blockIdx.x * 256 + threadIdx.x;
    if (i >= NN) return;
    int o = g_off[i] + g_boff[blockIdx.x];
    g_off[i] = o;
    g_cur[i] = o;
}
__global__ void k_fill(const int* __restrict__ ei) {
    int e = blockIdx.x * blockDim.x + threadIdx.x;
    if (e >= EE) return;
    int s = ld_idx(ei, e);
    int d = ld_idx(ei, EE + e);
    int pos = atomicAdd(&g_cur[d], 1);
    g_srcs[pos] = s;
}

// ---------------- GEMM1: x @ W1 (+ per-node attention scores) ----------------
__global__ void k_gemm1(const float* __restrict__ x, const float* __restrict__ W1,
                        const float* __restrict__ a_s, const float* __restrict__ a_d) {
    __shared__ float sx[16 * 64];        // 4 KB
    __shared__ float sW1T[256 * 36];     // 36 KB (one 32-k half, [c][k] padded)
    __shared__ float ses[16 * 4], sed[16 * 4];
    int n0 = blockIdx.x * 16;
    int t = threadIdx.x;
    for (int i = t; i < 16 * 64 / 4; i += 256)
        ((float4*)sx)[i] = ((const float4*)(x + n0 * 64))[i];
    if (t < 64) { ses[t] = 0.f; sed[t] = 0.f; }
    float acc[16];
#pragma unroll
    for (int n = 0; n < 16; n++) acc[n] = 0.f;
    for (int half = 0; half < 2; half++) {
        __syncthreads();
        for (int i = t; i < 32 * 256; i += 256) {
            int kk = i >> 8, cc = i & 255;
            sW1T[cc * 36 + kk] = W1[(half * 32 + kk) * 256 + cc];
        }
        __syncthreads();
#pragma unroll
        for (int k4 = 0; k4 < 8; k4++) {
            float4 w = *(float4*)&sW1T[t * 36 + k4 * 4];
#pragma unroll
            for (int n = 0; n < 16; n++) {
                float4 xv = *(float4*)&sx[n * 64 + half * 32 + k4 * 4];
                acc[n] = fmaf(w.x, xv.x, acc[n]);
                acc[n] = fmaf(w.y, xv.y, acc[n]);
                acc[n] = fmaf(w.z, xv.z, acc[n]);
                acc[n] = fmaf(w.w, xv.w, acc[n]);
            }
        }
    }
    __syncthreads();
    int h = t >> 6, c = t & 63;
    float asv = __ldg(&a_s[h * 64 + c]);
    float adv = __ldg(&a_d[h * 64 + c]);
#pragma unroll
    for (int n = 0; n < 16; n++) {
        g_h1[(n0 + n) * C1 + t] = acc[n];
        float vs = acc[n] * asv, vd = acc[n] * adv;
#pragma unroll
        for (int o = 16; o > 0; o >>= 1) {
            vs += __shfl_down_sync(0xffffffffu, vs, o);
            vd += __shfl_down_sync(0xffffffffu, vd, o);
        }
        if ((t & 31) == 0) { atomicAdd(&ses[n * 4 + h], vs); atomicAdd(&sed[n * 4 + h], vd); }
    }
    __syncthreads();
    if (t < 64) {
        int n = t >> 2, hh = t & 3;
        g_es1[(n0 + n) * 4 + hh] = ses[t];
        g_ed1[(n0 + n) * 4 + hh] = sed[t];
    }
}

// ---------------- Layer-1 aggregate per dst (CSR) + BN1 + ELU ----------------
__global__ void k_agg1(const float* __restrict__ b1, const float* __restrict__ g1,
                       const float* __restrict__ be1, const float* __restrict__ m1,
                       const float* __restrict__ v1) {
    __shared__ int   ssrc[32];
    __shared__ float sp[32 * 4];
    int d = blockIdx.x;
    int t = threadIdx.x;
    int off = g_off[d];
    int deg = g_off[d + 1] - off;
    int hsel = t >> 6;
    float acc = 0.f, den = 0.f;
    for (int base = 0; base < deg; base += 32) {
        int m = min(32, deg - base);
        if (t < m * 4) {
            int e = t >> 2, hh = t & 3;
            int s = g_srcs[off + base + e];
            if (hh == 0) ssrc[e] = s;
            sp[t] = __expf(lrelu(g_es1[s * 4 + hh] + g_ed1[d * 4 + hh]));
        }
        __syncthreads();
#pragma unroll 2
        for (int e = 0; e < m; e++) {
            float p = sp[e * 4 + hsel];
            int s = ssrc[e];
            acc = fmaf(p, g_h1[s * C1 + t], acc);
            den += p;
        }
        __syncthreads();
    }
    float ps = __expf(lrelu(g_es1[d * 4 + hsel] + g_ed1[d * 4 + hsel]));
    acc = fmaf(ps, g_h1[d * C1 + t], acc);
    den += ps;
    float val = acc / den + __ldg(&b1[t]);
    val = (val - __ldg(&m1[t])) * rsqrtf(__ldg(&v1[t]) + EPSBN) * __ldg(&g1[t]) + __ldg(&be1[t]);
    val = val > 0.f ? val : expm1f(val);
    g_y[d * C1 + t] = val;
}

// ---------------- GEMM2: y @ W2 (+ layer-2 scores) ---------------------------
__global__ void k_mid(const float* __restrict__ W2, const float* __restrict__ as2,
                      const float* __restrict__ ad2) {
    __shared__ float sy[16 * 256];       // 16 KB
    __shared__ float sW2T[64 * 68];      // 17 KB
    __shared__ float sh2[16 * 64];       // 4 KB
    int n0 = blockIdx.x * 16;
    int t = threadIdx.x;
    for (int i = t; i < 16 * 256 / 4; i += 256)
        ((float4*)sy)[i] = ((const float4*)(g_y + n0 * 256))[i];
    int c = t & 63, nq = t >> 6;
    float acc[4] = {0.f, 0.f, 0.f, 0.f};
    for (int q = 0; q < 4; q++) {
        __syncthreads();
        for (int i = t; i < 64 * 64; i += 256) {
            int kk = i >> 6, cc = i & 63;
            sW2T[cc * 68 + kk] = W2[(q * 64 + kk) * 64 + cc];
        }
        __syncthreads();
#pragma unroll
        for (int j = 0; j < 4; j++) {
            int n = nq + j * 4;
            float a = acc[j];
#pragma unroll
            for (int k4 = 0; k4 < 16; k4++) {
                float4 w  = *(float4*)&sW2T[c * 68 + k4 * 4];
                float4 yv = *(float4*)&sy[n * 256 + q * 64 + k4 * 4];
                a = fmaf(w.x, yv.x, a);
                a = fmaf(w.y, yv.y, a);
                a = fmaf(w.z, yv.z, a);
                a = fmaf(w.w, yv.w, a);
            }
            acc[j] = a;
        }
    }
    __syncthreads();
#pragma unroll
    for (int j = 0; j < 4; j++) {
        int n = nq + j * 4;
        g_h2[(n0 + n) * 64 + c] = acc[j];
        sh2[n * 64 + c] = acc[j];
    }
    __syncthreads();
    if (t < 16) {
        float vs = 0.f, vd = 0.f;
        for (int k = 0; k < 64; k++) {
            float hv = sh2[t * 64 + k];
            vs = fmaf(hv, __ldg(&as2[k]), vs);
            vd = fmaf(hv, __ldg(&ad2[k]), vd);
        }
        g_es2[n0 + t] = vs;
        g_ed2[n0 + t] = vd;
    }
}

// ---------------- Layer-2 aggregate: warp per dst, shuffle-broadcast p -------
// 8 warps/block = 8 dsts. Lane computes exp for ONE edge per 32-chunk, then
// p and src are shuffle-broadcast during accumulation. Lane owns 2 channels.
__global__ void k_agg2(const int* __restrict__ bat, const float* __restrict__ b2,
                       const float* __restrict__ g2, const float* __restrict__ be2,
                       const float* __restrict__ m2, const float* __restrict__ v2) {
    int warp = threadIdx.x >> 5;
    int lane = threadIdx.x & 31;
    int d = blockIdx.x * 8 + warp;
    if (d >= NN) return;
    int off = g_off[d];
    int deg = g_off[d + 1] - off;
    float edv = g_ed2[d];
    float2 acc = {0.f, 0.f};
    float den = 0.f;
    for (int base = 0; base < deg; base += 32) {
        int m = min(32, deg - base);
        int s = (lane < m) ? g_srcs[off + base + lane] : 0;
        float p = (lane < m) ? __expf(lrelu(g_es2[s] + edv)) : 0.f;
#pragma unroll 2
        for (int e = 0; e < m; e++) {
            float pe = __shfl_sync(0xffffffffu, p, e);
            int   se = __shfl_sync(0xffffffffu, s, e);
            float2 hv = *(const float2*)(g_h2 + se * 64 + lane * 2);
            acc.x = fmaf(pe, hv.x, acc.x);
            acc.y = fmaf(pe, hv.y, acc.y);
            den += pe;
        }
    }
    float ps = __expf(lrelu(g_es2[d] + edv));
    float2 hv = *(const float2*)(g_h2 + d * 64 + lane * 2);
    acc.x = fmaf(ps, hv.x, acc.x);
    acc.y = fmaf(ps, hv.y, acc.y);
    den += ps;
    float inv = 1.f / den;
    int g = ld_idx(bat, d);
#pragma unroll
    for (int j = 0; j < 2; j++) {
        int c = lane * 2 + j;
        float val = (j ? acc.y : acc.x) * inv + __ldg(&b2[c]);
        val = (val - __ldg(&m2[c])) * rsqrtf(__ldg(&v2[c]) + EPSBN) * __ldg(&g2[c]) + __ldg(&be2[c]);
        red_add_f32(&g_pool[g * 64 + c], val);
    }
    if (lane == 0) red_add_f32(&g_cnt[g], 1.f);
}

// ---------------- MLP head + log_softmax -------------------------------------
__global__ void k_head(const float* __restrict__ lw1, const float* __restrict__ lb1,
                       const float* __restrict__ lw2, const float* __restrict__ lb2,
                       float* __restrict__ out) {
    int g = threadIdx.x;
    if (g >= GG) return;
    float inv = 1.f / fmaxf(g_cnt[g], 1.f);
    float z1[HID / 2];
#pragma unroll 4
    for (int j = 0; j < HID / 2; j++) {
        float a = lb1[j];
        for (int k = 0; k < HID; k++)
            a = fmaf(g_pool[g * HID + k] * inv, lw1[k * (HID / 2) + j], a);
        z1[j] = fmaxf(a, 0.f);
    }
    float z2[NCLS];
#pragma unroll
    for (int cc = 0; cc < NCLS; cc++) {
        float a = lb2[cc];
        for (int j = 0; j < HID / 2; j++)
            a = fmaf(z1[j], lw2[j * NCLS + cc], a);
        z2[cc] = a;
    }
    float mx = fmaxf(z2[0], fmaxf(z2[1], z2[2]));
    float lse = mx + logf(expf(z2[0] - mx) + expf(z2[1] - mx) + expf(z2[2] - mx));
#pragma unroll
    for (int cc = 0; cc < NCLS; cc++) out[g * NCLS + cc] = z2[cc] - lse;
}

// ---------------- host launcher ----------------------------------------------
extern "C" void kernel_launch(void* const* d_in, const int* in_sizes, int n_in,
                              void* d_out, int out_size) {
    int IX, IEI, IB, IW1, IAS1, IAD1, IB1, IG1, IBE1, IM1, IV1,
        IW2, IAS2, IAD2, IB2, IG2, IBE2, IM2, IV2, ILW1, ILB1, ILW2, ILB2;
    if (n_in >= 3 && in_sizes[1] == 2 * EE) {
        IX = 0; IEI = 1; IB = 2; IW1 = 3; IAS1 = 4; IAD1 = 5; IB1 = 6; IG1 = 7; IBE1 = 8;
        IM1 = 9; IV1 = 10; IW2 = 11; IAS2 = 12; IAD2 = 13; IB2 = 14; IG2 = 15; IBE2 = 16;
        IM2 = 17; IV2 = 18; ILW1 = 19; ILB1 = 20; ILW2 = 21; ILB2 = 22;
    } else {
        IX = 0; IW1 = 1; IAS1 = 2; IAD1 = 3; IB1 = 4; IG1 = 5; IBE1 = 6; IM1 = 7; IV1 = 8;
        IW2 = 9; IAS2 = 10; IAD2 = 11; IB2 = 12; IG2 = 13; IBE2 = 14; IM2 = 15; IV2 = 16;
        ILW1 = 17; ILB1 = 18; ILW2 = 19; ILB2 = 20; IEI = 21; IB = 22;
    }

    const float* x   = (const float*)d_in[IX];
    const int*   ei  = (const int*)d_in[IEI];
    const int*   bat = (const int*)d_in[IB];
    const float* W1  = (const float*)d_in[IW1];
    const float* as1 = (const float*)d_in[IAS1];
    const float* ad1 = (const float*)d_in[IAD1];
    const float* b1  = (const float*)d_in[IB1];
    const float* g1  = (const float*)d_in[IG1];
    const float* be1 = (const float*)d_in[IBE1];
    const float* m1  = (const float*)d_in[IM1];
    const float* v1  = (const float*)d_in[IV1];
    const float* W2  = (const float*)d_in[IW2];
    const float* as2 = (const float*)d_in[IAS2];
    const float* ad2 = (const float*)d_in[IAD2];
    const float* b2  = (const float*)d_in[IB2];
    const float* g2  = (const float*)d_in[IG2];
    const float* be2 = (const float*)d_in[IBE2];
    const float* m2  = (const float*)d_in[IM2];
    const float* v2  = (const float*)d_in[IV2];
    const float* lw1 = (const float*)d_in[ILW1];
    const float* lb1 = (const float*)d_in[ILB1];
    const float* lw2 = (const float*)d_in[ILW2];
    const float* lb2 = (const float*)d_in[ILB2];
    float* out = (float*)d_out;

    k_detect<<<1, 32>>>(ei);
    k_zero<<<256, 256>>>();
    k_deg<<<(EE + 511) / 512, 512>>>(ei);
    k_scanA<<<SCAN_BLOCKS, 256>>>();
    k_scanB<<<1, 256>>>();
    k_scanC<<<SCAN_BLOCKS, 256>>>();
    k_fill<<<(EE + 511) / 512, 512>>>(ei);
    k_gemm1<<<NB_GEMM, 256>>>(x, W1, as1, ad1);
    k_agg1<<<NN, 256>>>(b1, g1, be1, m1, v1);
    k_mid<<<NB_GEMM, 256>>>(W2, as2, ad2);
    k_agg2<<<(NN + 7) / 8, 256>>>(bat, b2, g2, be2, m2, v2);
    k_head<<<1, 64>>>(lw1, lb1, lw2, lb2, out);
}

// round 8
// speedup vs baseline: 1.6243x; 1.1469x over previous
#include <cuda_runtime.h>
#include <cuda_fp16.h>

#define NN 50000
#define EE 800000
#define FIN 64
#define HID 64
#define HEADS 4
#define C1 256
#define GG 64
#define NCLS 3
#define EPSBN 1e-5f
#define SLOPE 0.2f

#define NB_GEMM 3125          // 50000/16 nodes-per-block
#define SCAN_BLOCKS 196       // ceil(50000/256)

// ---------------- scratch ----------------------------------------------------
__device__ __align__(16) __half2 g_h1h[NN * 128];  // layer1 features, half2 pairs
__device__ __align__(16) float   g_y[NN * C1];
__device__ __align__(16) float   g_es1[NN * HEADS];
__device__ __align__(16) float   g_ed1[NN * HEADS];
__device__ __align__(16) __half2 g_h2h[NN * 32];   // layer2 features, half2 pairs
__device__ float g_es2[NN];
__device__ float g_ed2[NN];
__device__ float g_pool[GG * HID];
__device__ float g_cnt[GG];
__device__ int   g_deg[NN];
__device__ int   g_off[NN + 1];
__device__ int   g_cur[NN];
__device__ int   g_srcs[EE];
__device__ int   g_bsum[SCAN_BLOCKS];
__device__ int   g_boff[SCAN_BLOCKS];
__device__ int   g_is64;

__device__ __forceinline__ void red_add_f32(float* addr, float a) {
    asm volatile("red.global.add.f32 [%0], %1;" :: "l"(addr), "f"(a) : "memory");
}
__device__ __forceinline__ float lrelu(float t) { return t > 0.f ? t : SLOPE * t; }

// ---------------- index dtype detection --------------------------------------
__global__ void k_detect(const int* ei) {
    if (threadIdx.x == 0) {
        int all0 = 1;
        for (int i = 0; i < 64; i++)
            if (ei[2 * i + 1] != 0) { all0 = 0; break; }
        g_is64 = all0;
    }
}
__device__ __forceinline__ int ld_idx(const int* p, int i) {
    return p[g_is64 ? 2 * i : i];
}

// ---------------- zero small accumulators ------------------------------------
__global__ void k_zero() {
    int i = blockIdx.x * blockDim.x + threadIdx.x;
    int stride = gridDim.x * blockDim.x;
    for (int j = i; j < NN; j += stride)       g_deg[j] = 0;
    for (int j = i; j < GG * HID; j += stride) g_pool[j] = 0.f;
    for (int j = i; j < GG; j += stride)       g_cnt[j] = 0.f;
}

// ---------------- CSR build ---------------------------------------------------
__global__ void k_deg(const int* __restrict__ ei) {
    int e = blockIdx.x * blockDim.x + threadIdx.x;
    if (e >= EE) return;
    atomicAdd(&g_deg[ld_idx(ei, EE + e)], 1);
}
__global__ void k_scanA() {
    __shared__ int s[256];
    int t = threadIdx.x;
    int i = blockIdx.x * 256 + t;
    int v = (i < NN) ? g_deg[i] : 0;
    s[t] = v; __syncthreads();
    for (int o = 1; o < 256; o <<= 1) {
        int u = (t >= o) ? s[t - o] : 0;
        __syncthreads(); s[t] += u; __syncthreads();
    }
    if (i < NN) g_off[i] = s[t] - v;
    if (t == 255) g_bsum[blockIdx.x] = s[255];
}
__global__ void k_scanB() {
    __shared__ int s[256];
    int t = threadIdx.x;
    int v = (t < SCAN_BLOCKS) ? g_bsum[t] : 0;
    s[t] = v; __syncthreads();
    for (int o = 1; o < 256; o <<= 1) {
        int u = (t >= o) ? s[t - o] : 0;
        __syncthreads(); s[t] += u; __syncthreads();
    }
    if (t < SCAN_BLOCKS) g_boff[t] = s[t] - v;
    if (t == 0) g_off[NN] = EE;
}
__global__ void k_scanC() {
    int i = blockIdx.x * 256 + threadIdx.x;
    if (i >= NN) return;
    int o = g_off[i] + g_boff[blockIdx.x];
    g_off[i] = o;
    g_cur[i] = o;
}
__global__ void k_fill(const int* __restrict__ ei) {
    int e = blockIdx.x * blockDim.x + threadIdx.x;
    if (e >= EE) return;
    int s = ld_idx(ei, e);
    int d = ld_idx(ei, EE + e);
    int pos = atomicAdd(&g_cur[d], 1);
    g_srcs[pos] = s;
}

// ---------------- GEMM1: x @ W1 (+ per-node attention scores) ----------------
__global__ void k_gemm1(const float* __restrict__ x, const float* __restrict__ W1,
                        const float* __restrict__ a_s, const float* __restrict__ a_d) {
    __shared__ float sx[16 * 64];        // 4 KB
    __shared__ float sW1T[256 * 36];     // 36 KB (one 32-k half, [c][k] padded)
    __shared__ float ses[16 * 4], sed[16 * 4];
    int n0 = blockIdx.x * 16;
    int t = threadIdx.x;
    for (int i = t; i < 16 * 64 / 4; i += 256)
        ((float4*)sx)[i] = ((const float4*)(x + n0 * 64))[i];
    if (t < 64) { ses[t] = 0.f; sed[t] = 0.f; }
    float acc[16];
#pragma unroll
    for (int n = 0; n < 16; n++) acc[n] = 0.f;
    for (int half = 0; half < 2; half++) {
        __syncthreads();
        for (int i = t; i < 32 * 256; i += 256) {
            int kk = i >> 8, cc = i & 255;
            sW1T[cc * 36 + kk] = W1[(half * 32 + kk) * 256 + cc];
        }
        __syncthreads();
#pragma unroll
        for (int k4 = 0; k4 < 8; k4++) {
            float4 w = *(float4*)&sW1T[t * 36 + k4 * 4];
#pragma unroll
            for (int n = 0; n < 16; n++) {
                float4 xv = *(float4*)&sx[n * 64 + half * 32 + k4 * 4];
                acc[n] = fmaf(w.x, xv.x, acc[n]);
                acc[n] = fmaf(w.y, xv.y, acc[n]);
                acc[n] = fmaf(w.z, xv.z, acc[n]);
                acc[n] = fmaf(w.w, xv.w, acc[n]);
            }
        }
    }
    __syncthreads();
    int h = t >> 6, c = t & 63;
    float asv = __ldg(&a_s[h * 64 + c]);
    float adv = __ldg(&a_d[h * 64 + c]);
#pragma unroll
    for (int n = 0; n < 16; n++) {
        float hi = __shfl_down_sync(0xffffffffu, acc[n], 1);
        if (!(t & 1)) g_h1h[(n0 + n) * 128 + (t >> 1)] = __floats2half2_rn(acc[n], hi);
        float vs = acc[n] * asv, vd = acc[n] * adv;
#pragma unroll
        for (int o = 16; o > 0; o >>= 1) {
            vs += __shfl_down_sync(0xffffffffu, vs, o);
            vd += __shfl_down_sync(0xffffffffu, vd, o);
        }
        if ((t & 31) == 0) { atomicAdd(&ses[n * 4 + h], vs); atomicAdd(&sed[n * 4 + h], vd); }
    }
    __syncthreads();
    if (t < 64) {
        int n = t >> 2, hh = t & 3;
        g_es1[(n0 + n) * 4 + hh] = ses[t];
        g_ed1[(n0 + n) * 4 + hh] = sed[t];
    }
}

// ---------------- Layer-1 aggregate per dst (CSR) + BN1 + ELU ----------------
// 128 threads/block; thread owns channel pair (2t, 2t+1) via one half2 load.
__global__ void k_agg1(const float* __restrict__ b1, const float* __restrict__ g1,
                       const float* __restrict__ be1, const float* __restrict__ m1,
                       const float* __restrict__ v1) {
    __shared__ int   ssrc[32];
    __shared__ float sp[32 * 4];
    int d = blockIdx.x;
    int t = threadIdx.x;                 // 0..127
    int off = g_off[d];
    int deg = g_off[d + 1] - off;
    int hsel = t >> 5;                   // head of channels (2t,2t+1)
    float accx = 0.f, accy = 0.f, den = 0.f;
    for (int base = 0; base < deg; base += 32) {
        int m = min(32, deg - base);
        {
            int e = t >> 2, hh = t & 3;
            if (e < m) {
                int s = g_srcs[off + base + e];
                if (hh == 0) ssrc[e] = s;
                sp[e * 4 + hh] = __expf(lrelu(g_es1[s * 4 + hh] + g_ed1[d * 4 + hh]));
            }
        }
        __syncthreads();
#pragma unroll 2
        for (int e = 0; e < m; e++) {
            float p = sp[e * 4 + hsel];
            float2 hv = __half22float2(g_h1h[ssrc[e] * 128 + t]);
            accx = fmaf(p, hv.x, accx);
            accy = fmaf(p, hv.y, accy);
            den += p;
        }
        __syncthreads();
    }
    float ps = __expf(lrelu(g_es1[d * 4 + hsel] + g_ed1[d * 4 + hsel]));
    float2 hv = __half22float2(g_h1h[d * 128 + t]);
    accx = fmaf(ps, hv.x, accx);
    accy = fmaf(ps, hv.y, accy);
    den += ps;
    float inv = 1.f / den;
    int c0 = 2 * t, c1 = 2 * t + 1;
    float v0 = accx * inv + __ldg(&b1[c0]);
    v0 = (v0 - __ldg(&m1[c0])) * rsqrtf(__ldg(&v1[c0]) + EPSBN) * __ldg(&g1[c0]) + __ldg(&be1[c0]);
    v0 = v0 > 0.f ? v0 : expm1f(v0);
    float v1v = accy * inv + __ldg(&b1[c1]);
    v1v = (v1v - __ldg(&m1[c1])) * rsqrtf(__ldg(&v1[c1]) + EPSBN) * __ldg(&g1[c1]) + __ldg(&be1[c1]);
    v1v = v1v > 0.f ? v1v : expm1f(v1v);
    g_y[d * C1 + c0] = v0;
    g_y[d * C1 + c1] = v1v;
}

// ---------------- GEMM2: y @ W2 (+ layer-2 scores) ---------------------------
__global__ void k_mid(const float* __restrict__ W2, const float* __restrict__ as2,
                      const float* __restrict__ ad2) {
    __shared__ float sy[16 * 256];       // 16 KB
    __shared__ float sW2T[64 * 68];      // 17 KB
    __shared__ float sh2[16 * 64];       // 4 KB
    int n0 = blockIdx.x * 16;
    int t = threadIdx.x;
    for (int i = t; i < 16 * 256 / 4; i += 256)
        ((float4*)sy)[i] = ((const float4*)(g_y + n0 * 256))[i];
    int c = t & 63, nq = t >> 6;
    float acc[4] = {0.f, 0.f, 0.f, 0.f};
    for (int q = 0; q < 4; q++) {
        __syncthreads();
        for (int i = t; i < 64 * 64; i += 256) {
            int kk = i >> 6, cc = i & 63;
            sW2T[cc * 68 + kk] = W2[(q * 64 + kk) * 64 + cc];
        }
        __syncthreads();
#pragma unroll
        for (int j = 0; j < 4; j++) {
            int n = nq + j * 4;
            float a = acc[j];
#pragma unroll
            for (int k4 = 0; k4 < 16; k4++) {
                float4 w  = *(float4*)&sW2T[c * 68 + k4 * 4];
                float4 yv = *(float4*)&sy[n * 256 + q * 64 + k4 * 4];
                a = fmaf(w.x, yv.x, a);
                a = fmaf(w.y, yv.y, a);
                a = fmaf(w.z, yv.z, a);
                a = fmaf(w.w, yv.w, a);
            }
            acc[j] = a;
        }
    }
    __syncthreads();
#pragma unroll
    for (int j = 0; j < 4; j++) {
        int n = nq + j * 4;
        float hi = __shfl_down_sync(0xffffffffu, acc[j], 1);
        if (!(c & 1)) g_h2h[(n0 + n) * 32 + (c >> 1)] = __floats2half2_rn(acc[j], hi);
        sh2[n * 64 + c] = acc[j];
    }
    __syncthreads();
    if (t < 16) {
        float vs = 0.f, vd = 0.f;
        for (int k = 0; k < 64; k++) {
            float hv = sh2[t * 64 + k];
            vs = fmaf(hv, __ldg(&as2[k]), vs);
            vd = fmaf(hv, __ldg(&ad2[k]), vd);
        }
        g_es2[n0 + t] = vs;
        g_ed2[n0 + t] = vd;
    }
}

// ---------------- Layer-2 aggregate: warp per dst, shuffle-broadcast p -------
__global__ void k_agg2(const int* __restrict__ bat, const float* __restrict__ b2,
                       const float* __restrict__ g2, const float* __restrict__ be2,
                       const float* __restrict__ m2, const float* __restrict__ v2) {
    int warp = threadIdx.x >> 5;
    int lane = threadIdx.x & 31;
    int d = blockIdx.x * 8 + warp;
    if (d >= NN) return;
    int off = g_off[d];
    int deg = g_off[d + 1] - off;
    float edv = g_ed2[d];
    float accx = 0.f, accy = 0.f, den = 0.f;
    for (int base = 0; base < deg; base += 32) {
        int m = min(32, deg - base);
        int s = (lane < m) ? g_srcs[off + base + lane] : 0;
        float p = (lane < m) ? __expf(lrelu(g_es2[s] + edv)) : 0.f;
#pragma unroll 2
        for (int e = 0; e < m; e++) {
            float pe = __shfl_sync(0xffffffffu, p, e);
            int   se = __shfl_sync(0xffffffffu, s, e);
            float2 hv = __half22float2(g_h2h[se * 32 + lane]);
            accx = fmaf(pe, hv.x, accx);
            accy = fmaf(pe, hv.y, accy);
            den += pe;
        }
    }
    float ps = __expf(lrelu(g_es2[d] + edv));
    float2 hv = __half22float2(g_h2h[d * 32 + lane]);
    accx = fmaf(ps, hv.x, accx);
    accy = fmaf(ps, hv.y, accy);
    den += ps;
    float inv = 1.f / den;
    int g = ld_idx(bat, d);
    int c0 = lane * 2, c1 = lane * 2 + 1;
    float val0 = accx * inv + __ldg(&b2[c0]);
    val0 = (val0 - __ldg(&m2[c0])) * rsqrtf(__ldg(&v2[c0]) + EPSBN) * __ldg(&g2[c0]) + __ldg(&be2[c0]);
    red_add_f32(&g_pool[g * 64 + c0], val0);
    float val1 = accy * inv + __ldg(&b2[c1]);
    val1 = (val1 - __ldg(&m2[c1])) * rsqrtf(__ldg(&v2[c1]) + EPSBN) * __ldg(&g2[c1]) + __ldg(&be2[c1]);
    red_add_f32(&g_pool[g * 64 + c1], val1);
    if (lane == 0) red_add_f32(&g_cnt[g], 1.f);
}

// ---------------- MLP head + log_softmax -------------------------------------
__global__ void k_head(const float* __restrict__ lw1, const float* __restrict__ lb1,
                       const float* __restrict__ lw2, const float* __restrict__ lb2,
                       float* __restrict__ out) {
    int g = threadIdx.x;
    if (g >= GG) return;
    float inv = 1.f / fmaxf(g_cnt[g], 1.f);
    float z1[HID / 2];
#pragma unroll 4
    for (int j = 0; j < HID / 2; j++) {
        float a = lb1[j];
        for (int k = 0; k < HID; k++)
            a = fmaf(g_pool[g * HID + k] * inv, lw1[k * (HID / 2) + j], a);
        z1[j] = fmaxf(a, 0.f);
    }
    float z2[NCLS];
#pragma unroll
    for (int cc = 0; cc < NCLS; cc++) {
        float a = lb2[cc];
        for (int j = 0; j < HID / 2; j++)
            a = fmaf(z1[j], lw2[j * NCLS + cc], a);
        z2[cc] = a;
    }
    float mx = fmaxf(z2[0], fmaxf(z2[1], z2[2]));
    float lse = mx + logf(expf(z2[0] - mx) + expf(z2[1] - mx) + expf(z2[2] - mx));
#pragma unroll
    for (int cc = 0; cc < NCLS; cc++) out[g * NCLS + cc] = z2[cc] - lse;
}

// ---------------- host launcher ----------------------------------------------
extern "C" void kernel_launch(void* const* d_in, const int* in_sizes, int n_in,
                              void* d_out, int out_size) {
    int IX, IEI, IB, IW1, IAS1, IAD1, IB1, IG1, IBE1, IM1, IV1,
        IW2, IAS2, IAD2, IB2, IG2, IBE2, IM2, IV2, ILW1, ILB1, ILW2, ILB2;
    if (n_in >= 3 && in_sizes[1] == 2 * EE) {
        IX = 0; IEI = 1; IB = 2; IW1 = 3; IAS1 = 4; IAD1 = 5; IB1 = 6; IG1 = 7; IBE1 = 8;
        IM1 = 9; IV1 = 10; IW2 = 11; IAS2 = 12; IAD2 = 13; IB2 = 14; IG2 = 15; IBE2 = 16;
        IM2 = 17; IV2 = 18; ILW1 = 19; ILB1 = 20; ILW2 = 21; ILB2 = 22;
    } else {
        IX = 0; IW1 = 1; IAS1 = 2; IAD1 = 3; IB1 = 4; IG1 = 5; IBE1 = 6; IM1 = 7; IV1 = 8;
        IW2 = 9; IAS2 = 10; IAD2 = 11; IB2 = 12; IG2 = 13; IBE2 = 14; IM2 = 15; IV2 = 16;
        ILW1 = 17; ILB1 = 18; ILW2 = 19; ILB2 = 20; IEI = 21; IB = 22;
    }

    const float* x   = (const float*)d_in[IX];
    const int*   ei  = (const int*)d_in[IEI];
    const int*   bat = (const int*)d_in[IB];
    const float* W1  = (const float*)d_in[IW1];
    const float* as1 = (const float*)d_in[IAS1];
    const float* ad1 = (const float*)d_in[IAD1];
    const float* b1  = (const float*)d_in[IB1];
    const float* g1  = (const float*)d_in[IG1];
    const float* be1 = (const float*)d_in[IBE1];
    const float* m1  = (const float*)d_in[IM1];
    const float* v1  = (const float*)d_in[IV1];
    const float* W2  = (const float*)d_in[IW2];
    const float* as2 = (const float*)d_in[IAS2];
    const float* ad2 = (const float*)d_in[IAD2];
    const float* b2  = (const float*)d_in[IB2];
    const float* g2  = (const float*)d_in[IG2];
    const float* be2 = (const float*)d_in[IBE2];
    const float* m2  = (const float*)d_in[IM2];
    const float* v2  = (const float*)d_in[IV2];
    const float* lw1 = (const float*)d_in[ILW1];
    const float* lb1 = (const float*)d_in[ILB1];
    const float* lw2 = (const float*)d_in[ILW2];
    const float* lb2 = (const float*)d_in[ILB2];
    float* out = (float*)d_out;

    k_detect<<<1, 32>>>(ei);
    k_zero<<<256, 256>>>();
    k_deg<<<(EE + 511) / 512, 512>>>(ei);
    k_gemm1<<<NB_GEMM, 256>>>(x, W1, as1, ad1);   // moved early: profile target + overlap-friendly
    k_scanA<<<SCAN_BLOCKS, 256>>>();
    k_scanB<<<1, 256>>>();
    k_scanC<<<SCAN_BLOCKS, 256>>>();
    k_fill<<<(EE + 511) / 512, 512>>>(ei);
    k_agg1<<<NN, 128>>>(b1, g1, be1, m1, v1);
    k_mid<<<NB_GEMM, 256>>>(W2, as2, ad2);
    k_agg2<<<(NN + 7) / 8, 256>>>(bat, b2, g2, be2, m2, v2);
    k_head<<<1, 64>>>(lw1, lb1, lw2, lb2, out);
}

// round 9
// speedup vs baseline: 2.0655x; 1.2717x over previous
#include <cuda_runtime.h>
#include <cuda_fp16.h>

#define NN 50000
#define EE 800000
#define FIN 64
#define HID 64
#define HEADS 4
#define C1 256
#define GG 64
#define NCLS 3
#define EPSBN 1e-5f
#define SLOPE 0.2f

#define NB_GEMM 782           // ceil(50000/64)
#define SCAN_BLOCKS 196       // ceil(50000/256)

// ---------------- scratch ----------------------------------------------------
__device__ __align__(16) __half2 g_h1h[NN * 128];  // layer1 features (half2 pairs)
__device__ __align__(16) __half2 g_yh[NN * 128];   // post BN/ELU activations (half2)
__device__ __align__(16) float   g_es1[NN * HEADS];
__device__ __align__(16) float   g_ed1[NN * HEADS];
__device__ __align__(16) __half2 g_h2h[NN * 32];   // layer2 features (half2)
__device__ float g_es2[NN];
__device__ float g_ed2[NN];
__device__ float g_pool[GG * HID];
__device__ float g_cnt[GG];
__device__ int   g_deg[NN];
__device__ int   g_off[NN + 1];
__device__ int   g_cur[NN];
__device__ int   g_srcs[EE];
__device__ int   g_bsum[SCAN_BLOCKS];
__device__ int   g_boff[SCAN_BLOCKS];
__device__ int   g_is64;

__device__ __forceinline__ void red_add_f32(float* addr, float a) {
    asm volatile("red.global.add.f32 [%0], %1;" :: "l"(addr), "f"(a) : "memory");
}
__device__ __forceinline__ float lrelu(float t) { return t > 0.f ? t : SLOPE * t; }
__device__ __forceinline__ int ld_idx(const int* p, int i) {
    return p[g_is64 ? 2 * i : i];
}

// ---------------- zero + index dtype detection --------------------------------
__global__ void k_zero(const int* ei) {
    int i = blockIdx.x * blockDim.x + threadIdx.x;
    int stride = gridDim.x * blockDim.x;
    if (blockIdx.x == 0 && threadIdx.x == 0) {
        int all0 = 1;
        for (int j = 0; j < 64; j++)
            if (ei[2 * j + 1] != 0) { all0 = 0; break; }
        g_is64 = all0;
    }
    for (int j = i; j < NN; j += stride)       g_deg[j] = 0;
    for (int j = i; j < GG * HID; j += stride) g_pool[j] = 0.f;
    for (int j = i; j < GG; j += stride)       g_cnt[j] = 0.f;
}

// ---------------- CSR build ---------------------------------------------------
__global__ void k_deg(const int* __restrict__ ei) {
    int e = blockIdx.x * blockDim.x + threadIdx.x;
    if (e >= EE) return;
    atomicAdd(&g_deg[ld_idx(ei, EE + e)], 1);
}
__global__ void k_scanA() {
    __shared__ int s[256];
    int t = threadIdx.x;
    int i = blockIdx.x * 256 + t;
    int v = (i < NN) ? g_deg[i] : 0;
    s[t] = v; __syncthreads();
    for (int o = 1; o < 256; o <<= 1) {
        int u = (t >= o) ? s[t - o] : 0;
        __syncthreads(); s[t] += u; __syncthreads();
    }
    if (i < NN) g_off[i] = s[t] - v;
    if (t == 255) g_bsum[blockIdx.x] = s[255];
}
__global__ void k_scanB() {
    __shared__ int s[256];
    int t = threadIdx.x;
    int v = (t < SCAN_BLOCKS) ? g_bsum[t] : 0;
    s[t] = v; __syncthreads();
    for (int o = 1; o < 256; o <<= 1) {
        int u = (t >= o) ? s[t - o] : 0;
        __syncthreads(); s[t] += u; __syncthreads();
    }
    if (t < SCAN_BLOCKS) g_boff[t] = s[t] - v;
    if (t == 0) g_off[NN] = EE;
}
__global__ void k_scanC() {
    int i = blockIdx.x * 256 + threadIdx.x;
    if (i >= NN) return;
    int o = g_off[i] + g_boff[blockIdx.x];
    g_off[i] = o;
    g_cur[i] = o;
}
__global__ void k_fill(const int* __restrict__ ei) {
    int e = blockIdx.x * blockDim.x + threadIdx.x;
    if (e >= EE) return;
    int s = ld_idx(ei, e);
    int d = ld_idx(ei, EE + e);
    int pos = atomicAdd(&g_cur[d], 1);
    g_srcs[pos] = s;
}

// ---------------- GEMM1: x @ W1 (+ per-node attention scores) ----------------
// 64 nodes/block, 256 threads. Thread = (ng = t>>6 node group of 16, c = t&63
// channel group of 4). Register tile 16 nodes x 4 channels.
// Weight tile layout sWg[cgroup][k][4ch], row pad 33: lane stride 132 words
// == 4 mod 32 -> each 8-lane LDS.128 phase covers all 32 banks (conflict-free).
__global__ __launch_bounds__(256) void k_gemm1(const float* __restrict__ x,
                                               const float* __restrict__ W1,
                                               const float* __restrict__ a_s,
                                               const float* __restrict__ a_d) {
    __shared__ float sx[64 * 64];           // 16 KB
    __shared__ float sWg[64 * 33 * 4];      // 33.8 KB (one 32-k half)
    int n0 = blockIdx.x * 64;
    int t = threadIdx.x;
    int c = t & 63, ng = t >> 6;

    for (int i = t; i < 1024; i += 256) {   // 64 nodes * 16 float4
        int node = i >> 4;
        float4 v = make_float4(0.f, 0.f, 0.f, 0.f);
        if (n0 + node < NN) v = ((const float4*)x)[(n0 + node) * 16 + (i & 15)];
        ((float4*)sx)[i] = v;
    }

    float acc[16][4];
#pragma unroll
    for (int n = 0; n < 16; n++)
#pragma unroll
        for (int j = 0; j < 4; j++) acc[n][j] = 0.f;

    for (int half = 0; half < 2; half++) {
        __syncthreads();
        for (int i = t; i < 8192; i += 256) {      // 32 k * 256 ch
            int ch = i & 255, kk = i >> 8;
            int cg = ch >> 2, j = ch & 3;
            sWg[(cg * 33 + kk) * 4 + j] = W1[(half * 32 + kk) * 256 + ch];
        }
        __syncthreads();
#pragma unroll
        for (int k4 = 0; k4 < 8; k4++) {
            float4 wa = *(float4*)&sWg[(c * 33 + k4 * 4 + 0) * 4];
            float4 wb = *(float4*)&sWg[(c * 33 + k4 * 4 + 1) * 4];
            float4 wc = *(float4*)&sWg[(c * 33 + k4 * 4 + 2) * 4];
            float4 wd = *(float4*)&sWg[(c * 33 + k4 * 4 + 3) * 4];
#pragma unroll
            for (int n = 0; n < 16; n++) {
                float4 xv = *(float4*)&sx[(ng * 16 + n) * 64 + half * 32 + k4 * 4];
                acc[n][0] = fmaf(wa.x, xv.x, fmaf(wb.x, xv.y, fmaf(wc.x, xv.z, fmaf(wd.x, xv.w, acc[n][0]))));
                acc[n][1] = fmaf(wa.y, xv.x, fmaf(wb.y, xv.y, fmaf(wc.y, xv.z, fmaf(wd.y, xv.w, acc[n][1]))));
                acc[n][2] = fmaf(wa.z, xv.x, fmaf(wb.z, xv.y, fmaf(wc.z, xv.z, fmaf(wd.z, xv.w, acc[n][2]))));
                acc[n][3] = fmaf(wa.w, xv.x, fmaf(wb.w, xv.y, fmaf(wc.w, xv.z, fmaf(wd.w, xv.w, acc[n][3]))));
            }
        }
    }

    // epilogue: half2 store + attention scores
    int h = c >> 4;                         // head (0..3); within-head ch = 4*(c&15)+j
    float4 asv = *(const float4*)&a_s[h * 64 + 4 * (c & 15)];
    float4 adv = *(const float4*)&a_d[h * 64 + 4 * (c & 15)];
#pragma unroll
    for (int n = 0; n < 16; n++) {
        int node = n0 + ng * 16 + n;
        __half2 p[2];
        p[0] = __floats2half2_rn(acc[n][0], acc[n][1]);
        p[1] = __floats2half2_rn(acc[n][2], acc[n][3]);
        if (node < NN) *(uint2*)&g_h1h[node * 128 + 2 * c] = *(uint2*)p;
        float vs = acc[n][0] * asv.x + acc[n][1] * asv.y + acc[n][2] * asv.z + acc[n][3] * asv.w;
        float vd = acc[n][0] * adv.x + acc[n][1] * adv.y + acc[n][2] * adv.z + acc[n][3] * adv.w;
#pragma unroll
        for (int o = 8; o > 0; o >>= 1) {
            vs += __shfl_down_sync(0xffffffffu, vs, o, 16);
            vd += __shfl_down_sync(0xffffffffu, vd, o, 16);
        }
        if ((c & 15) == 0 && node < NN) {
            g_es1[node * 4 + h] = vs;
            g_ed1[node * 4 + h] = vd;
        }
    }
}

// ---------------- Layer-1 aggregate per dst (CSR) + BN1 + ELU ----------------
__global__ void k_agg1(const float* __restrict__ b1, const float* __restrict__ g1,
                       const float* __restrict__ be1, const float* __restrict__ m1,
                       const float* __restrict__ v1) {
    __shared__ int   ssrc[32];
    __shared__ float sp[32 * 4];
    int d = blockIdx.x;
    int t = threadIdx.x;                 // 0..127
    int off = g_off[d];
    int deg = g_off[d + 1] - off;
    int hsel = t >> 5;
    float accx = 0.f, accy = 0.f, den = 0.f;
    for (int base = 0; base < deg; base += 32) {
        int m = min(32, deg - base);
        {
            int e = t >> 2, hh = t & 3;
            if (e < m) {
                int s = g_srcs[off + base + e];
                if (hh == 0) ssrc[e] = s;
                sp[e * 4 + hh] = __expf(lrelu(g_es1[s * 4 + hh] + g_ed1[d * 4 + hh]));
            }
        }
        __syncthreads();
#pragma unroll 2
        for (int e = 0; e < m; e++) {
            float p = sp[e * 4 + hsel];
            float2 hv = __half22float2(g_h1h[ssrc[e] * 128 + t]);
            accx = fmaf(p, hv.x, accx);
            accy = fmaf(p, hv.y, accy);
            den += p;
        }
        __syncthreads();
    }
    float ps = __expf(lrelu(g_es1[d * 4 + hsel] + g_ed1[d * 4 + hsel]));
    float2 hv = __half22float2(g_h1h[d * 128 + t]);
    accx = fmaf(ps, hv.x, accx);
    accy = fmaf(ps, hv.y, accy);
    den += ps;
    float inv = 1.f / den;
    int c0 = 2 * t, c1 = 2 * t + 1;
    float v0 = accx * inv + __ldg(&b1[c0]);
    v0 = (v0 - __ldg(&m1[c0])) * rsqrtf(__ldg(&v1[c0]) + EPSBN) * __ldg(&g1[c0]) + __ldg(&be1[c0]);
    v0 = v0 > 0.f ? v0 : expm1f(v0);
    float v1v = accy * inv + __ldg(&b1[c1]);
    v1v = (v1v - __ldg(&m1[c1])) * rsqrtf(__ldg(&v1[c1]) + EPSBN) * __ldg(&g1[c1]) + __ldg(&be1[c1]);
    v1v = v1v > 0.f ? v1v : expm1f(v1v);
    g_yh[d * 128 + t] = __floats2half2_rn(v0, v1v);
}

// ---------------- GEMM2: y @ W2 (+ layer-2 scores) ---------------------------
// 64 nodes/block, 256 threads = (ng = t>>4 of 16 groups x 4 nodes, c = t&15
// channel group of 4). Activations staged as half2 (32 KB); W2 in 4 k-quarters
// with interleaved [cgroup][k][4] layout, pad 65 (conflict-free; see gemm1).
__global__ __launch_bounds__(256) void k_mid(const float* __restrict__ W2,
                                             const float* __restrict__ as2,
                                             const float* __restrict__ ad2) {
    __shared__ __half2 sy[64 * 128];        // 32 KB
    __shared__ float   sWg[16 * 65 * 4];    // 16.6 KB (one 64-k quarter)
    int n0 = blockIdx.x * 64;
    int t = threadIdx.x;
    int c = t & 15, ng = t >> 4;

    for (int i = t; i < 2048; i += 256) {   // 64 nodes * 32 uint4
        int node = i >> 5;
        uint4 v = make_uint4(0u, 0u, 0u, 0u);
        if (n0 + node < NN) v = ((const uint4*)g_yh)[(n0 + node) * 32 + (i & 31)];
        ((uint4*)sy)[i] = v;
    }

    float acc[4][4];
#pragma unroll
    for (int n = 0; n < 4; n++)
#pragma unroll
        for (int j = 0; j < 4; j++) acc[n][j] = 0.f;

    for (int q = 0; q < 4; q++) {
        __syncthreads();
        for (int i = t; i < 4096; i += 256) {      // 64 k * 64 ch
            int ch = i & 63, kk = i >> 6;
            int cg = ch >> 2, j = ch & 3;
            sWg[(cg * 65 + kk) * 4 + j] = W2[(q * 64 + kk) * 64 + ch];
        }
        __syncthreads();
#pragma unroll
        for (int k8 = 0; k8 < 8; k8++) {
            float4 w[8];
#pragma unroll
            for (int i = 0; i < 8; i++)
                w[i] = *(float4*)&sWg[(c * 65 + k8 * 8 + i) * 4];
#pragma unroll
            for (int n = 0; n < 4; n++) {
                int nl = ng * 4 + n;
                uint4 raw = *(uint4*)&sy[nl * 128 + q * 32 + k8 * 4];
                __half2 hh[4];
                *(uint4*)hh = raw;
                float2 f0 = __half22float2(hh[0]);
                float2 f1 = __half22float2(hh[1]);
                float2 f2 = __half22float2(hh[2]);
                float2 f3 = __half22float2(hh[3]);
#pragma unroll
                for (int j = 0; j < 4; j++) {
                    float a = acc[n][j];
                    a = fmaf(((float*)&w[0])[j], f0.x, a);
                    a = fmaf(((float*)&w[1])[j], f0.y, a);
                    a = fmaf(((float*)&w[2])[j], f1.x, a);
                    a = fmaf(((float*)&w[3])[j], f1.y, a);
                    a = fmaf(((float*)&w[4])[j], f2.x, a);
                    a = fmaf(((float*)&w[5])[j], f2.y, a);
                    a = fmaf(((float*)&w[6])[j], f3.x, a);
                    a = fmaf(((float*)&w[7])[j], f3.y, a);
                    acc[n][j] = a;
                }
            }
        }
    }

    // epilogue: half2 store + layer-2 scores
    float4 asv = *(const float4*)&as2[4 * c];
    float4 adv = *(const float4*)&ad2[4 * c];
#pragma unroll
    for (int n = 0; n < 4; n++) {
        int node = n0 + ng * 4 + n;
        __half2 p[2];
        p[0] = __floats2half2_rn(acc[n][0], acc[n][1]);
        p[1] = __floats2half2_rn(acc[n][2], acc[n][3]);
        if (node < NN) *(uint2*)&g_h2h[node * 32 + 2 * c] = *(uint2*)p;
        float vs = acc[n][0] * asv.x + acc[n][1] * asv.y + acc[n][2] * asv.z + acc[n][3] * asv.w;
        float vd = acc[n][0] * adv.x + acc[n][1] * adv.y + acc[n][2] * adv.z + acc[n][3] * adv.w;
#pragma unroll
        for (int o = 8; o > 0; o >>= 1) {
            vs += __shfl_down_sync(0xffffffffu, vs, o, 16);
            vd += __shfl_down_sync(0xffffffffu, vd, o, 16);
        }
        if (c == 0 && node < NN) {
            g_es2[node] = vs;
            g_ed2[node] = vd;
        }
    }
}

// ---------------- Layer-2 aggregate: warp per dst, shuffle-broadcast p -------
__global__ void k_agg2(const int* __restrict__ bat, const float* __restrict__ b2,
                       const float* __restrict__ g2, const float* __restrict__ be2,
                       const float* __restrict__ m2, const float* __restrict__ v2) {
    int warp = threadIdx.x >> 5;
    int lane = threadIdx.x & 31;
    int d = blockIdx.x * 8 + warp;
    if (d >= NN) return;
    int off = g_off[d];
    int deg = g_off[d + 1] - off;
    float edv = g_ed2[d];
    float accx = 0.f, accy = 0.f, den = 0.f;
    for (int base = 0; base < deg; base += 32) {
        int m = min(32, deg - base);
        int s = (lane < m) ? g_srcs[off + base + lane] : 0;
        float p = (lane < m) ? __expf(lrelu(g_es2[s] + edv)) : 0.f;
#pragma unroll 2
        for (int e = 0; e < m; e++) {
            float pe = __shfl_sync(0xffffffffu, p, e);
            int   se = __shfl_sync(0xffffffffu, s, e);
            float2 hv = __half22float2(g_h2h[se * 32 + lane]);
            accx = fmaf(pe, hv.x, accx);
            accy = fmaf(pe, hv.y, accy);
            den += pe;
        }
    }
    float ps = __expf(lrelu(g_es2[d] + edv));
    float2 hv = __half22float2(g_h2h[d * 32 + lane]);
    accx = fmaf(ps, hv.x, accx);
    accy = fmaf(ps, hv.y, accy);
    den += ps;
    float inv = 1.f / den;
    int g = ld_idx(bat, d);
    int c0 = lane * 2, c1 = lane * 2 + 1;
    float val0 = accx * inv + __ldg(&b2[c0]);
    val0 = (val0 - __ldg(&m2[c0])) * rsqrtf(__ldg(&v2[c0]) + EPSBN) * __ldg(&g2[c0]) + __ldg(&be2[c0]);
    red_add_f32(&g_pool[g * 64 + c0], val0);
    float val1 = accy * inv + __ldg(&b2[c1]);
    val1 = (val1 - __ldg(&m2[c1])) * rsqrtf(__ldg(&v2[c1]) + EPSBN) * __ldg(&g2[c1]) + __ldg(&be2[c1]);
    red_add_f32(&g_pool[g * 64 + c1], val1);
    if (lane == 0) red_add_f32(&g_cnt[g], 1.f);
}

// ---------------- MLP head + log_softmax -------------------------------------
__global__ void k_head(const float* __restrict__ lw1, const float* __restrict__ lb1,
                       const float* __restrict__ lw2, const float* __restrict__ lb2,
                       float* __restrict__ out) {
    int g = threadIdx.x;
    if (g >= GG) return;
    float inv = 1.f / fmaxf(g_cnt[g], 1.f);
    float z1[HID / 2];
#pragma unroll 4
    for (int j = 0; j < HID / 2; j++) {
        float a = lb1[j];
        for (int k = 0; k < HID; k++)
            a = fmaf(g_pool[g * HID + k] * inv, lw1[k * (HID / 2) + j], a);
        z1[j] = fmaxf(a, 0.f);
    }
    float z2[NCLS];
#pragma unroll
    for (int cc = 0; cc < NCLS; cc++) {
        float a = lb2[cc];
        for (int j = 0; j < HID / 2; j++)
            a = fmaf(z1[j], lw2[j * NCLS + cc], a);
        z2[cc] = a;
    }
    float mx = fmaxf(z2[0], fmaxf(z2[1], z2[2]));
    float lse = mx + logf(expf(z2[0] - mx) + expf(z2[1] - mx) + expf(z2[2] - mx));
#pragma unroll
    for (int cc = 0; cc < NCLS; cc++) out[g * NCLS + cc] = z2[cc] - lse;
}

// ---------------- host launcher ----------------------------------------------
extern "C" void kernel_launch(void* const* d_in, const int* in_sizes, int n_in,
                              void* d_out, int out_size) {
    int IX, IEI, IB, IW1, IAS1, IAD1, IB1, IG1, IBE1, IM1, IV1,
        IW2, IAS2, IAD2, IB2, IG2, IBE2, IM2, IV2, ILW1, ILB1, ILW2, ILB2;
    if (n_in >= 3 && in_sizes[1] == 2 * EE) {
        IX = 0; IEI = 1; IB = 2; IW1 = 3; IAS1 = 4; IAD1 = 5; IB1 = 6; IG1 = 7; IBE1 = 8;
        IM1 = 9; IV1 = 10; IW2 = 11; IAS2 = 12; IAD2 = 13; IB2 = 14; IG2 = 15; IBE2 = 16;
        IM2 = 17; IV2 = 18; ILW1 = 19; ILB1 = 20; ILW2 = 21; ILB2 = 22;
    } else {
        IX = 0; IW1 = 1; IAS1 = 2; IAD1 = 3; IB1 = 4; IG1 = 5; IBE1 = 6; IM1 = 7; IV1 = 8;
        IW2 = 9; IAS2 = 10; IAD2 = 11; IB2 = 12; IG2 = 13; IBE2 = 14; IM2 = 15; IV2 = 16;
        ILW1 = 17; ILB1 = 18; ILW2 = 19; ILB2 = 20; IEI = 21; IB = 22;
    }

    const float* x   = (const float*)d_in[IX];
    const int*   ei  = (const int*)d_in[IEI];
    const int*   bat = (const int*)d_in[IB];
    const float* W1  = (const float*)d_in[IW1];
    const float* as1 = (const float*)d_in[IAS1];
    const float* ad1 = (const float*)d_in[IAD1];
    const float* b1  = (const float*)d_in[IB1];
    const float* g1  = (const float*)d_in[IG1];
    const float* be1 = (const float*)d_in[IBE1];
    const float* m1  = (const float*)d_in[IM1];
    const float* v1  = (const float*)d_in[IV1];
    const float* W2  = (const float*)d_in[IW2];
    const float* as2 = (const float*)d_in[IAS2];
    const float* ad2 = (const float*)d_in[IAD2];
    const float* b2  = (const float*)d_in[IB2];
    const float* g2  = (const float*)d_in[IG2];
    const float* be2 = (const float*)d_in[IBE2];
    const float* m2  = (const float*)d_in[IM2];
    const float* v2  = (const float*)d_in[IV2];
    const float* lw1 = (const float*)d_in[ILW1];
    const float* lb1 = (const float*)d_in[ILB1];
    const float* lw2 = (const float*)d_in[ILW2];
    const float* lb2 = (const float*)d_in[ILB2];
    float* out = (float*)d_out;

    k_zero<<<256, 256>>>(ei);
    k_deg<<<(EE + 511) / 512, 512>>>(ei);
    k_scanA<<<SCAN_BLOCKS, 256>>>();
    k_gemm1<<<NB_GEMM, 256>>>(x, W1, as1, ad1);   // launch #4: ncu capture slot
    k_scanB<<<1, 256>>>();
    k_scanC<<<SCAN_BLOCKS, 256>>>();
    k_fill<<<(EE + 511) / 512, 512>>>(ei);
    k_agg1<<<NN, 128>>>(b1, g1, be1, m1, v1);
    k_mid<<<NB_GEMM, 256>>>(W2, as2, ad2);
    k_agg2<<<(NN + 7) / 8, 256>>>(bat, b2, g2, be2, m2, v2);
    k_head<<<1, 64>>>(lw1, lb1, lw2, lb2, out);
}

// round 10
// speedup vs baseline: 2.1204x; 1.0266x over previous
#include <cuda_runtime.h>
#include <cuda_fp16.h>

#define NN 50000
#define EE 800000
#define FIN 64
#define HID 64
#define HEADS 4
#define C1 256
#define GG 64
#define NCLS 3
#define EPSBN 1e-5f
#define SLOPE 0.2f

#define NB_GEMM 782           // ceil(50000/64)
#define SCAN_BLOCKS 196       // ceil(50000/256)

typedef unsigned long long ull;

// ---------------- scratch ----------------------------------------------------
__device__ __align__(16) __half2 g_h1h[NN * 128];  // layer1 features (half2 pairs)
__device__ __align__(16) __half2 g_yh[NN * 128];   // post BN/ELU activations (half2)
__device__ __align__(16) float   g_es1[NN * HEADS];
__device__ __align__(16) float   g_ed1[NN * HEADS];
__device__ __align__(16) __half2 g_h2h[NN * 32];   // layer2 features (half2)
__device__ float g_es2[NN];
__device__ float g_ed2[NN];
__device__ float g_pool[GG * HID];
__device__ float g_cnt[GG];
__device__ int   g_deg[NN];
__device__ int   g_off[NN + 1];
__device__ int   g_cur[NN];
__device__ int   g_srcs[EE];
__device__ int   g_bsum[SCAN_BLOCKS];
__device__ int   g_boff[SCAN_BLOCKS];
__device__ int   g_is64;

__device__ __forceinline__ void red_add_f32(float* addr, float a) {
    asm volatile("red.global.add.f32 [%0], %1;" :: "l"(addr), "f"(a) : "memory");
}
__device__ __forceinline__ float lrelu(float t) { return t > 0.f ? t : SLOPE * t; }
__device__ __forceinline__ int ld_idx(const int* p, int i) {
    return p[g_is64 ? 2 * i : i];
}

// packed fp32x2 FMA (sm_103a): d = a*b + d elementwise on 2 packed floats
__device__ __forceinline__ void fma_x2(ull& d, ull a, ull b) {
    asm("fma.rn.f32x2 %0, %1, %2, %0;" : "+l"(d) : "l"(a), "l"(b));
}
__device__ __forceinline__ ull pack_dup(float w) {
    ull r; asm("mov.b64 %0, {%1, %1};" : "=l"(r) : "f"(w)); return r;
}
__device__ __forceinline__ float2 unpack_x2(ull v) {
    float2 f; asm("mov.b64 {%0, %1}, %2;" : "=f"(f.x), "=f"(f.y) : "l"(v)); return f;
}

// ---------------- zero + index dtype detection --------------------------------
__global__ void k_zero(const int* ei) {
    int i = blockIdx.x * blockDim.x + threadIdx.x;
    int stride = gridDim.x * blockDim.x;
    if (blockIdx.x == 0 && threadIdx.x == 0) {
        int all0 = 1;
        for (int j = 0; j < 64; j++)
            if (ei[2 * j + 1] != 0) { all0 = 0; break; }
        g_is64 = all0;
    }
    for (int j = i; j < NN; j += stride)       g_deg[j] = 0;
    for (int j = i; j < GG * HID; j += stride) g_pool[j] = 0.f;
    for (int j = i; j < GG; j += stride)       g_cnt[j] = 0.f;
}

// ---------------- CSR build ---------------------------------------------------
__global__ void k_deg(const int* __restrict__ ei) {
    int e = blockIdx.x * blockDim.x + threadIdx.x;
    if (e >= EE) return;
    atomicAdd(&g_deg[ld_idx(ei, EE + e)], 1);
}
__global__ void k_scanA() {
    __shared__ int s[256];
    int t = threadIdx.x;
    int i = blockIdx.x * 256 + t;
    int v = (i < NN) ? g_deg[i] : 0;
    s[t] = v; __syncthreads();
    for (int o = 1; o < 256; o <<= 1) {
        int u = (t >= o) ? s[t - o] : 0;
        __syncthreads(); s[t] += u; __syncthreads();
    }
    if (i < NN) g_off[i] = s[t] - v;
    if (t == 255) g_bsum[blockIdx.x] = s[255];
}
__global__ void k_scanB() {
    __shared__ int s[256];
    int t = threadIdx.x;
    int v = (t < SCAN_BLOCKS) ? g_bsum[t] : 0;
    s[t] = v; __syncthreads();
    for (int o = 1; o < 256; o <<= 1) {
        int u = (t >= o) ? s[t - o] : 0;
        __syncthreads(); s[t] += u; __syncthreads();
    }
    if (t < SCAN_BLOCKS) g_boff[t] = s[t] - v;
    if (t == 0) g_off[NN] = EE;
}
__global__ void k_scanC() {
    int i = blockIdx.x * 256 + threadIdx.x;
    if (i >= NN) return;
    int o = g_off[i] + g_boff[blockIdx.x];
    g_off[i] = o;
    g_cur[i] = o;
}
__global__ void k_fill(const int* __restrict__ ei) {
    int e = blockIdx.x * blockDim.x + threadIdx.x;
    if (e >= EE) return;
    int s = ld_idx(ei, e);
    int d = ld_idx(ei, EE + e);
    int pos = atomicAdd(&g_cur[d], 1);
    g_srcs[pos] = s;
}

// ---------------- GEMM1: x @ W1 via packed f32x2 FMA -------------------------
// 64 nodes/block, 256 threads: c = t&63 (4 output channels), ng = t>>6
// (16 nodes = 8 node-pairs). x staged TRANSPOSED as float2[k][node-pair] so a
// 64-bit operand holds the same k-value for 2 nodes; weights dup-packed per k.
__global__ __launch_bounds__(256) void k_gemm1(const float* __restrict__ x,
                                               const float* __restrict__ W1,
                                               const float* __restrict__ a_s,
                                               const float* __restrict__ a_d) {
    __shared__ float2 sx2[64 * 32];         // [k][np] 16 KB
    __shared__ float  sWg[64 * 33 * 4];     // 33.8 KB (one 32-k half, padded)
    int n0 = blockIdx.x * 64;
    int t = threadIdx.x;
    int c = t & 63, ng = t >> 6;

    // stage x transposed into node-pair layout
    for (int i = t; i < 512; i += 256) {    // 32 np * 16 k4
        int np = i & 31, k4 = i >> 5;
        int na = n0 + 2 * np, nb = na + 1;
        float4 va = make_float4(0.f, 0.f, 0.f, 0.f), vb = va;
        if (na < NN) va = ((const float4*)x)[na * 16 + k4];
        if (nb < NN) vb = ((const float4*)x)[nb * 16 + k4];
        sx2[(k4 * 4 + 0) * 32 + np] = make_float2(va.x, vb.x);
        sx2[(k4 * 4 + 1) * 32 + np] = make_float2(va.y, vb.y);
        sx2[(k4 * 4 + 2) * 32 + np] = make_float2(va.z, vb.z);
        sx2[(k4 * 4 + 3) * 32 + np] = make_float2(va.w, vb.w);
    }

    ull acc2[8][4];
#pragma unroll
    for (int np = 0; np < 8; np++)
#pragma unroll
        for (int j = 0; j < 4; j++) acc2[np][j] = 0ull;

    for (int half = 0; half < 2; half++) {
        __syncthreads();
        for (int i = t; i < 8192; i += 256) {      // 32 k * 256 ch
            int ch = i & 255, kk = i >> 8;
            int cg = ch >> 2, j = ch & 3;
            sWg[(cg * 33 + kk) * 4 + j] = W1[(half * 32 + kk) * 256 + ch];
        }
        __syncthreads();
#pragma unroll
        for (int k4 = 0; k4 < 8; k4++) {
            float4 wrow[4];
#pragma unroll
            for (int kk = 0; kk < 4; kk++)
                wrow[kk] = *(float4*)&sWg[(c * 33 + k4 * 4 + kk) * 4];
#pragma unroll
            for (int kk = 0; kk < 4; kk++) {
                ull w2[4];
                w2[0] = pack_dup(wrow[kk].x);
                w2[1] = pack_dup(wrow[kk].y);
                w2[2] = pack_dup(wrow[kk].z);
                w2[3] = pack_dup(wrow[kk].w);
                const ulonglong2* row =
                    (const ulonglong2*)&sx2[(half * 32 + k4 * 4 + kk) * 32 + ng * 8];
                ulonglong2 u0 = row[0], u1 = row[1], u2 = row[2], u3 = row[3];
                ull xv[8] = {u0.x, u0.y, u1.x, u1.y, u2.x, u2.y, u3.x, u3.y};
#pragma unroll
                for (int np = 0; np < 8; np++) {
#pragma unroll
                    for (int j = 0; j < 4; j++)
                        fma_x2(acc2[np][j], xv[np], w2[j]);
                }
            }
        }
    }

    // unpack + epilogue (half2 store + attention scores)
    int h = c >> 4;
    float4 asv = *(const float4*)&a_s[h * 64 + 4 * (c & 15)];
    float4 adv = *(const float4*)&a_d[h * 64 + 4 * (c & 15)];
#pragma unroll
    for (int np = 0; np < 8; np++) {
        float accA[4], accB[4];
#pragma unroll
        for (int j = 0; j < 4; j++) {
            float2 f = unpack_x2(acc2[np][j]);
            accA[j] = f.x; accB[j] = f.y;
        }
#pragma unroll
        for (int half = 0; half < 2; half++) {
            float* a = half ? accB : accA;
            int node = n0 + ng * 16 + 2 * np + half;
            __half2 p[2];
            p[0] = __floats2half2_rn(a[0], a[1]);
            p[1] = __floats2half2_rn(a[2], a[3]);
            if (node < NN) *(uint2*)&g_h1h[node * 128 + 2 * c] = *(uint2*)p;
            float vs = a[0] * asv.x + a[1] * asv.y + a[2] * asv.z + a[3] * asv.w;
            float vd = a[0] * adv.x + a[1] * adv.y + a[2] * adv.z + a[3] * adv.w;
#pragma unroll
            for (int o = 8; o > 0; o >>= 1) {
                vs += __shfl_down_sync(0xffffffffu, vs, o, 16);
                vd += __shfl_down_sync(0xffffffffu, vd, o, 16);
            }
            if ((c & 15) == 0 && node < NN) {
                g_es1[node * 4 + h] = vs;
                g_ed1[node * 4 + h] = vd;
            }
        }
    }
}

// ---------------- Layer-1 aggregate: warp per (dst, head), shuffle p ---------
// 128 threads = 4 warps; warp w owns head w of dst blockIdx.x. Lane owns
// channel pair (64w+2l, +1) = half2 index w*32+l. No smem, no block syncs.
__global__ void k_agg1(const float* __restrict__ b1, const float* __restrict__ g1,
                       const float* __restrict__ be1, const float* __restrict__ m1,
                       const float* __restrict__ v1) {
    int d = blockIdx.x;
    int w = threadIdx.x >> 5;
    int lane = threadIdx.x & 31;
    int off = g_off[d];
    int deg = g_off[d + 1] - off;
    float edv = g_ed1[d * 4 + w];
    float accx = 0.f, accy = 0.f, den = 0.f;
    for (int base = 0; base < deg; base += 32) {
        int m = min(32, deg - base);
        int s = (lane < m) ? g_srcs[off + base + lane] : 0;
        float p = (lane < m) ? __expf(lrelu(g_es1[s * 4 + w] + edv)) : 0.f;
#pragma unroll 4
        for (int e = 0; e < m; e++) {
            float pe = __shfl_sync(0xffffffffu, p, e);
            int   se = __shfl_sync(0xffffffffu, s, e);
            float2 hv = __half22float2(g_h1h[se * 128 + w * 32 + lane]);
            accx = fmaf(pe, hv.x, accx);
            accy = fmaf(pe, hv.y, accy);
            den += pe;
        }
    }
    float ps = __expf(lrelu(g_es1[d * 4 + w] + edv));
    float2 hv = __half22float2(g_h1h[d * 128 + w * 32 + lane]);
    accx = fmaf(ps, hv.x, accx);
    accy = fmaf(ps, hv.y, accy);
    den += ps;
    float inv = 1.f / den;
    int c0 = w * 64 + 2 * lane, c1 = c0 + 1;
    float v0 = accx * inv + __ldg(&b1[c0]);
    v0 = (v0 - __ldg(&m1[c0])) * rsqrtf(__ldg(&v1[c0]) + EPSBN) * __ldg(&g1[c0]) + __ldg(&be1[c0]);
    v0 = v0 > 0.f ? v0 : expm1f(v0);
    float v1v = accy * inv + __ldg(&b1[c1]);
    v1v = (v1v - __ldg(&m1[c1])) * rsqrtf(__ldg(&v1[c1]) + EPSBN) * __ldg(&g1[c1]) + __ldg(&be1[c1]);
    v1v = v1v > 0.f ? v1v : expm1f(v1v);
    g_yh[d * 128 + w * 32 + lane] = __floats2half2_rn(v0, v1v);
}

// ---------------- GEMM2: y @ W2 (+ layer-2 scores) ---------------------------
__global__ __launch_bounds__(256) void k_mid(const float* __restrict__ W2,
                                             const float* __restrict__ as2,
                                             const float* __restrict__ ad2) {
    __shared__ __half2 sy[64 * 128];        // 32 KB
    __shared__ float   sWg[16 * 65 * 4];    // 16.6 KB (one 64-k quarter)
    int n0 = blockIdx.x * 64;
    int t = threadIdx.x;
    int c = t & 15, ng = t >> 4;

    for (int i = t; i < 2048; i += 256) {   // 64 nodes * 32 uint4
        int node = i >> 5;
        uint4 v = make_uint4(0u, 0u, 0u, 0u);
        if (n0 + node < NN) v = ((const uint4*)g_yh)[(n0 + node) * 32 + (i & 31)];
        ((uint4*)sy)[i] = v;
    }

    float acc[4][4];
#pragma unroll
    for (int n = 0; n < 4; n++)
#pragma unroll
        for (int j = 0; j < 4; j++) acc[n][j] = 0.f;

    for (int q = 0; q < 4; q++) {
        __syncthreads();
        for (int i = t; i < 4096; i += 256) {      // 64 k * 64 ch
            int ch = i & 63, kk = i >> 6;
            int cg = ch >> 2, j = ch & 3;
            sWg[(cg * 65 + kk) * 4 + j] = W2[(q * 64 + kk) * 64 + ch];
        }
        __syncthreads();
#pragma unroll
        for (int k8 = 0; k8 < 8; k8++) {
            float4 w[8];
#pragma unroll
            for (int i = 0; i < 8; i++)
                w[i] = *(float4*)&sWg[(c * 65 + k8 * 8 + i) * 4];
#pragma unroll
            for (int n = 0; n < 4; n++) {
                int nl = ng * 4 + n;
                uint4 raw = *(uint4*)&sy[nl * 128 + q * 32 + k8 * 4];
                __half2 hh[4];
                *(uint4*)hh = raw;
                float2 f0 = __half22float2(hh[0]);
                float2 f1 = __half22float2(hh[1]);
                float2 f2 = __half22float2(hh[2]);
                float2 f3 = __half22float2(hh[3]);
#pragma unroll
                for (int j = 0; j < 4; j++) {
                    float a = acc[n][j];
                    a = fmaf(((float*)&w[0])[j], f0.x, a);
                    a = fmaf(((float*)&w[1])[j], f0.y, a);
                    a = fmaf(((float*)&w[2])[j], f1.x, a);
                    a = fmaf(((float*)&w[3])[j], f1.y, a);
                    a = fmaf(((float*)&w[4])[j], f2.x, a);
                    a = fmaf(((float*)&w[5])[j], f2.y, a);
                    a = fmaf(((float*)&w[6])[j], f3.x, a);
                    a = fmaf(((float*)&w[7])[j], f3.y, a);
                    acc[n][j] = a;
                }
            }
        }
    }

    float4 asv = *(const float4*)&as2[4 * c];
    float4 adv = *(const float4*)&ad2[4 * c];
#pragma unroll
    for (int n = 0; n < 4; n++) {
        int node = n0 + ng * 4 + n;
        __half2 p[2];
        p[0] = __floats2half2_rn(acc[n][0], acc[n][1]);
        p[1] = __floats2half2_rn(acc[n][2], acc[n][3]);
        if (node < NN) *(uint2*)&g_h2h[node * 32 + 2 * c] = *(uint2*)p;
        float vs = acc[n][0] * asv.x + acc[n][1] * asv.y + acc[n][2] * asv.z + acc[n][3] * asv.w;
        float vd = acc[n][0] * adv.x + acc[n][1] * adv.y + acc[n][2] * adv.z + acc[n][3] * adv.w;
#pragma unroll
        for (int o = 8; o > 0; o >>= 1) {
            vs += __shfl_down_sync(0xffffffffu, vs, o, 16);
            vd += __shfl_down_sync(0xffffffffu, vd, o, 16);
        }
        if (c == 0 && node < NN) {
            g_es2[node] = vs;
            g_ed2[node] = vd;
        }
    }
}

// ---------------- Layer-2 aggregate: warp per dst, shuffle-broadcast p -------
__global__ void k_agg2(const int* __restrict__ bat, const float* __restrict__ b2,
                       const float* __restrict__ g2, const float* __restrict__ be2,
                       const float* __restrict__ m2, const float* __restrict__ v2) {
    int warp = threadIdx.x >> 5;
    int lane = threadIdx.x & 31;
    int d = blockIdx.x * 8 + warp;
    if (d >= NN) return;
    int off = g_off[d];
    int deg = g_off[d + 1] - off;
    float edv = g_ed2[d];
    float accx = 0.f, accy = 0.f, den = 0.f;
    for (int base = 0; base < deg; base += 32) {
        int m = min(32, deg - base);
        int s = (lane < m) ? g_srcs[off + base + lane] : 0;
        float p = (lane < m) ? __expf(lrelu(g_es2[s] + edv)) : 0.f;
#pragma unroll 4
        for (int e = 0; e < m; e++) {
            float pe = __shfl_sync(0xffffffffu, p, e);
            int   se = __shfl_sync(0xffffffffu, s, e);
            float2 hv = __half22float2(g_h2h[se * 32 + lane]);
            accx = fmaf(pe, hv.x, accx);
            accy = fmaf(pe, hv.y, accy);
            den += pe;
        }
    }
    float ps = __expf(lrelu(g_es2[d] + edv));
    float2 hv = __half22float2(g_h2h[d * 32 + lane]);
    accx = fmaf(ps, hv.x, accx);
    accy = fmaf(ps, hv.y, accy);
    den += ps;
    float inv = 1.f / den;
    int g = ld_idx(bat, d);
    int c0 = lane * 2, c1 = lane * 2 + 1;
    float val0 = accx * inv + __ldg(&b2[c0]);
    val0 = (val0 - __ldg(&m2[c0])) * rsqrtf(__ldg(&v2[c0]) + EPSBN) * __ldg(&g2[c0]) + __ldg(&be2[c0]);
    red_add_f32(&g_pool[g * 64 + c0], val0);
    float val1 = accy * inv + __ldg(&b2[c1]);
    val1 = (val1 - __ldg(&m2[c1])) * rsqrtf(__ldg(&v2[c1]) + EPSBN) * __ldg(&g2[c1]) + __ldg(&be2[c1]);
    red_add_f32(&g_pool[g * 64 + c1], val1);
    if (lane == 0) red_add_f32(&g_cnt[g], 1.f);
}

// ---------------- MLP head + log_softmax -------------------------------------
__global__ void k_head(const float* __restrict__ lw1, const float* __restrict__ lb1,
                       const float* __restrict__ lw2, const float* __restrict__ lb2,
                       float* __restrict__ out) {
    int g = threadIdx.x;
    if (g >= GG) return;
    float inv = 1.f / fmaxf(g_cnt[g], 1.f);
    float z1[HID / 2];
#pragma unroll 4
    for (int j = 0; j < HID / 2; j++) {
        float a = lb1[j];
        for (int k = 0; k < HID; k++)
            a = fmaf(g_pool[g * HID + k] * inv, lw1[k * (HID / 2) + j], a);
        z1[j] = fmaxf(a, 0.f);
    }
    float z2[NCLS];
#pragma unroll
    for (int cc = 0; cc < NCLS; cc++) {
        float a = lb2[cc];
        for (int j = 0; j < HID / 2; j++)
            a = fmaf(z1[j], lw2[j * NCLS + cc], a);
        z2[cc] = a;
    }
    float mx = fmaxf(z2[0], fmaxf(z2[1], z2[2]));
    float lse = mx + logf(expf(z2[0] - mx) + expf(z2[1] - mx) + expf(z2[2] - mx));
#pragma unroll
    for (int cc = 0; cc < NCLS; cc++) out[g * NCLS + cc] = z2[cc] - lse;
}

// ---------------- host launcher ----------------------------------------------
extern "C" void kernel_launch(void* const* d_in, const int* in_sizes, int n_in,
                              void* d_out, int out_size) {
    int IX, IEI, IB, IW1, IAS1, IAD1, IB1, IG1, IBE1, IM1, IV1,
        IW2, IAS2, IAD2, IB2, IG2, IBE2, IM2, IV2, ILW1, ILB1, ILW2, ILB2;
    if (n_in >= 3 && in_sizes[1] == 2 * EE) {
        IX = 0; IEI = 1; IB = 2; IW1 = 3; IAS1 = 4; IAD1 = 5; IB1 = 6; IG1 = 7; IBE1 = 8;
        IM1 = 9; IV1 = 10; IW2 = 11; IAS2 = 12; IAD2 = 13; IB2 = 14; IG2 = 15; IBE2 = 16;
        IM2 = 17; IV2 = 18; ILW1 = 19; ILB1 = 20; ILW2 = 21; ILB2 = 22;
    } else {
        IX = 0; IW1 = 1; IAS1 = 2; IAD1 = 3; IB1 = 4; IG1 = 5; IBE1 = 6; IM1 = 7; IV1 = 8;
        IW2 = 9; IAS2 = 10; IAD2 = 11; IB2 = 12; IG2 = 13; IBE2 = 14; IM2 = 15; IV2 = 16;
        ILW1 = 17; ILB1 = 18; ILW2 = 19; ILB2 = 20; IEI = 21; IB = 22;
    }

    const float* x   = (const float*)d_in[IX];
    const int*   ei  = (const int*)d_in[IEI];
    const int*   bat = (const int*)d_in[IB];
    const float* W1  = (const float*)d_in[IW1];
    const float* as1 = (const float*)d_in[IAS1];
    const float* ad1 = (const float*)d_in[IAD1];
    const float* b1  = (const float*)d_in[IB1];
    const float* g1  = (const float*)d_in[IG1];
    const float* be1 = (const float*)d_in[IBE1];
    const float* m1  = (const float*)d_in[IM1];
    const float* v1  = (const float*)d_in[IV1];
    const float* W2  = (const float*)d_in[IW2];
    const float* as2 = (const float*)d_in[IAS2];
    const float* ad2 = (const float*)d_in[IAD2];
    const float* b2  = (const float*)d_in[IB2];
    const float* g2  = (const float*)d_in[IG2];
    const float* be2 = (const float*)d_in[IBE2];
    const float* m2  = (const float*)d_in[IM2];
    const float* v2  = (const float*)d_in[IV2];
    const float* lw1 = (const float*)d_in[ILW1];
    const float* lb1 = (const float*)d_in[ILB1];
    const float* lw2 = (const float*)d_in[ILW2];
    const float* lb2 = (const float*)d_in[ILB2];
    float* out = (float*)d_out;

    k_zero<<<256, 256>>>(ei);
    k_deg<<<(EE + 511) / 512, 512>>>(ei);
    k_scanA<<<SCAN_BLOCKS, 256>>>();
    k_gemm1<<<NB_GEMM, 256>>>(x, W1, as1, ad1);   // launch #4: ncu capture slot
    k_scanB<<<1, 256>>>();
    k_scanC<<<SCAN_BLOCKS, 256>>>();
    k_fill<<<(EE + 511) / 512, 512>>>(ei);
    k_agg1<<<NN, 128>>>(b1, g1, be1, m1, v1);
    k_mid<<<NB_GEMM, 256>>>(W2, as2, ad2);
    k_agg2<<<(NN + 7) / 8, 256>>>(bat, b2, g2, be2, m2, v2);
    k_head<<<1, 64>>>(lw1, lb1, lw2, lb2, out);
}